// round 13
// baseline (speedup 1.0000x reference)
#include <cuda_runtime.h>
#include <cuda_bf16.h>
#include <cstdint>

#define N_BATCH 4
#define C_DIM   512
#define C_W     256            // C_DIM/2 f16x2 words per row
#define T_DIM   4096
#define NTOK    (N_BATCH * T_DIM)   // 16384
#define H_HEADS 8
#define DH      64
#define CHUNK_SZ 64
#define NEG_INF (-1e9f)

// ---------------- proj GEMM tiling (128x64, BK=32, 3-stage) --------------------
#define PBM 128
#define PBNP 64                // proj N tile
#define NKT (C_DIM / 32)       // 16 k-tiles of 32
#define WPITCH 20              // u32 per smem row (80 B)
#define AP_U32 (128 * WPITCH)  // 2560
#define BP_U32 (64 * WPITCH)   // 1280
#define PSTG (AP_U32 + BP_U32) // 3840 u32 (15 KB)
#define NSTAGE 3
#define PSMEM_BYTES (NSTAGE * PSTG * 4)      // 46080

// ---------------- out GEMM tiling (128x128, BK=32, 3-stage) --------------------
#define PBN 128
#define A_U32 (128 * WPITCH)   // 2560
#define STAGE32 (2 * A_U32)    // 5120 u32 (20 KB)
#define OSMEM_BYTES (NSTAGE * STAGE32 * 4)   // 61440

// ---------------- fp16 attention tiling ---------------------------------------
#define AP2 68
#define ABUF2 (16 * AP2 * 2)
#define ASMEM2 ((3 * ABUF2 + 64) * 4)

// ---------------- scratch (fp16 packed as u32 words) ---------------------------
__device__ __align__(16) uint32_t g_QP16[(size_t)NTOK * C_W];
__device__ __align__(16) uint32_t g_KP16[(size_t)NTOK * C_W];
__device__ __align__(16) uint32_t g_VP16[(size_t)NTOK * C_W];
__device__ __align__(16) uint32_t g_AO16[(size_t)NTOK * C_W];
__device__ __align__(16) uint32_t g_W16[(size_t)2048 * C_W];   // 0-1535 Win, 1536-2047 Wout

// ---------------- helpers ------------------------------------------------------
__device__ __forceinline__ uint32_t pack_f16x2(float lo, float hi) {
    uint32_t r;
    asm("cvt.rn.f16x2.f32 %0, %1, %2;" : "=r"(r) : "f"(hi), "f"(lo));
    return r;
}

__device__ __forceinline__ uint32_t prmt_u32(uint32_t a, uint32_t b, uint32_t sel) {
    uint32_t r;
    asm("prmt.b32 %0, %1, %2, %3;" : "=r"(r) : "r"(a), "r"(b), "r"(sel));
    return r;
}

__device__ __forceinline__ void mma_f16(float* c,
                                        uint32_t a0, uint32_t a1, uint32_t a2, uint32_t a3,
                                        uint32_t b0, uint32_t b1) {
    asm volatile(
        "mma.sync.aligned.m16n8k16.row.col.f32.f16.f16.f32 "
        "{%0,%1,%2,%3}, {%4,%5,%6,%7}, {%8,%9}, {%0,%1,%2,%3};\n"
        : "+f"(c[0]), "+f"(c[1]), "+f"(c[2]), "+f"(c[3])
        : "r"(a0), "r"(a1), "r"(a2), "r"(a3), "r"(b0), "r"(b1));
}

__device__ __forceinline__ void ldsm_x4(uint32_t& r0, uint32_t& r1, uint32_t& r2,
                                        uint32_t& r3, uint32_t addr) {
    asm volatile("ldmatrix.sync.aligned.m8n8.x4.shared.b16 {%0,%1,%2,%3}, [%4];"
                 : "=r"(r0), "=r"(r1), "=r"(r2), "=r"(r3) : "r"(addr));
}

#define CP_ASYNC16(dst, src) \
    asm volatile("cp.async.cg.shared.global [%0], [%1], 16;" :: "r"(dst), "l"(src))
#define CP_COMMIT() asm volatile("cp.async.commit_group;")
#define CP_WAIT0()  asm volatile("cp.async.wait_group 0;" ::: "memory")
#define CP_WAIT1()  asm volatile("cp.async.wait_group 1;" ::: "memory")

// ---- mma over one BK=32 stage, warp tile 64x32, 80B pitch ----------------------
__device__ __forceinline__ void mma_tile_64x32(uint32_t sA, uint32_t sB,
                                               float acc[4][4][4],
                                               int wm, int wn, int lane) {
    int rA = wm * 64 + (lane & 7) + ((lane >> 3) & 1) * 8;
    int cA = ((lane >> 4) & 1) * 16;
    int rB = wn * 32 + (lane & 7) + ((lane >> 4) & 1) * 8;
    int cB = ((lane >> 3) & 1) * 16;
    #pragma unroll
    for (int ks = 0; ks < 2; ks++) {
        uint32_t a[4][4], b[2][4];
        #pragma unroll
        for (int mt = 0; mt < 4; mt++)
            ldsm_x4(a[mt][0], a[mt][1], a[mt][2], a[mt][3],
                    sA + (uint32_t)(rA + mt * 16) * 80 + cA + ks * 32);
        #pragma unroll
        for (int nb = 0; nb < 2; nb++)
            ldsm_x4(b[nb][0], b[nb][1], b[nb][2], b[nb][3],
                    sB + (uint32_t)(rB + nb * 16) * 80 + cB + ks * 32);
        #pragma unroll
        for (int mt = 0; mt < 4; mt++)
            #pragma unroll
            for (int nb = 0; nb < 2; nb++) {
                mma_f16(acc[mt][2 * nb],     a[mt][0], a[mt][1], a[mt][2], a[mt][3],
                        b[nb][0], b[nb][1]);
                mma_f16(acc[mt][2 * nb + 1], a[mt][0], a[mt][1], a[mt][2], a[mt][3],
                        b[nb][2], b[nb][3]);
            }
    }
}

// ---------------- weight pre-pack ----------------------------------------------
__global__ void pack_weights(const float* __restrict__ Win, const float* __restrict__ Wout)
{
    int i = blockIdx.x * 256 + threadIdx.x;
    int row = i >> 8, kw = i & 255;
    const float* src = (row < 1536) ? (Win + (size_t)row * C_DIM + 2 * kw)
                                    : (Wout + (size_t)(row - 1536) * C_DIM + 2 * kw);
    float2 f = *(const float2*)src;
    g_W16[i] = pack_f16x2(f.x, f.y);
}

// ---------------- GEMM: 3 projections, 128x64 tile, 3 CTAs/SM -------------------
__global__ void __launch_bounds__(128, 3) gemm_proj_v6(
    const float* __restrict__ qin, const float* __restrict__ kin,
    const float* __restrict__ vin, const float* __restrict__ b_in)
{
    extern __shared__ uint32_t sm[];
    int z = blockIdx.z;
    const float* A = (z == 0) ? qin : (z == 1) ? kin : vin;
    uint32_t* Cout16 = (z == 0) ? g_QP16 : (z == 1) ? g_KP16 : g_VP16;
    const float* bias = b_in + z * C_DIM;

    int g0 = blockIdx.x * PBM, bn = blockIdx.y;
    int n = g0 / T_DIM, t0 = g0 % T_DIM;
    const float* Abase = A + (size_t)n * C_DIM * T_DIM + t0;
    const uint32_t* Wb = g_W16 + (size_t)(z * 512 + bn * PBNP) * C_W;

    int tid = threadIdx.x, lane = tid & 31, wid = tid >> 5;
    int wm = wid >> 1, wn = wid & 1, q2 = lane & 3, rG = lane >> 2;
    uint32_t sbase = (uint32_t)__cvta_generic_to_shared(sm);

    float acc[4][4][4];
    #pragma unroll
    for (int a = 0; a < 4; a++)
        #pragma unroll
        for (int b = 0; b < 4; b++)
            #pragma unroll
            for (int c = 0; c < 4; c++) acc[a][b][c] = 0.f;

    // A staging ownership (verified R8 pattern): contiguous 512B warp LDGs
    int m0 = (tid & 31) * 4, kw0 = (tid >> 5) * 4;
    // B cp.async ownership: 64 rows, 2 chunks per thread
    int brow = tid >> 1, bco = (tid & 1) * 8;   // word offset 0 or 8

    float4 av[8];

    // prologue: stages 0 and 1
    #pragma unroll
    for (int s = 0; s < 2; s++) {
        int c0 = s * 32 + 2 * kw0;
        #pragma unroll
        for (int cr = 0; cr < 8; cr++)
            av[cr] = *(const float4*)(Abase + (size_t)(c0 + cr) * T_DIM + m0);
        uint32_t d = sbase + (s * PSTG + AP_U32) * 4 + brow * 80 + bco * 4;
        const uint32_t* sp = Wb + (size_t)brow * C_W + s * 16 + bco;
        CP_ASYNC16(d, sp);
        CP_ASYNC16(d + 16, sp + 4);
        CP_COMMIT();
        uint32_t* buf = sm + s * PSTG;
        const float* fv = (const float*)av;
        #pragma unroll
        for (int i = 0; i < 4; i++) {
            uint4 u;
            u.x = pack_f16x2(fv[0 + i],  fv[4 + i]);
            u.y = pack_f16x2(fv[8 + i],  fv[12 + i]);
            u.z = pack_f16x2(fv[16 + i], fv[20 + i]);
            u.w = pack_f16x2(fv[24 + i], fv[28 + i]);
            *(uint4*)(buf + (m0 + i) * WPITCH + kw0) = u;
        }
    }

    for (int kt = 0; kt < NKT; kt++) {
        if (kt + 1 < NKT) CP_WAIT1(); else CP_WAIT0();
        __syncthreads();
        bool pf = (kt + 2 < NKT);
        if (pf) {
            int c0 = (kt + 2) * 32 + 2 * kw0;
            #pragma unroll
            for (int cr = 0; cr < 8; cr++)
                av[cr] = *(const float4*)(Abase + (size_t)(c0 + cr) * T_DIM + m0);
            int st = (kt + 2) % NSTAGE;
            uint32_t d = sbase + (st * PSTG + AP_U32) * 4 + brow * 80 + bco * 4;
            const uint32_t* sp = Wb + (size_t)brow * C_W + (kt + 2) * 16 + bco;
            CP_ASYNC16(d, sp);
            CP_ASYNC16(d + 16, sp + 4);
            CP_COMMIT();
        }
        int p = kt % NSTAGE;
        mma_tile_64x32(sbase + p * PSTG * 4, sbase + (p * PSTG + AP_U32) * 4,
                       acc, wm, wn, lane);
        if (pf) {
            uint32_t* buf = sm + ((kt + 2) % NSTAGE) * PSTG;
            const float* fv = (const float*)av;
            #pragma unroll
            for (int i = 0; i < 4; i++) {
                uint4 u;
                u.x = pack_f16x2(fv[0 + i],  fv[4 + i]);
                u.y = pack_f16x2(fv[8 + i],  fv[12 + i]);
                u.z = pack_f16x2(fv[16 + i], fv[20 + i]);
                u.w = pack_f16x2(fv[24 + i], fv[28 + i]);
                *(uint4*)(buf + (m0 + i) * WPITCH + kw0) = u;
            }
        }
    }

    // epilogue: packed fp16 output [g][cw]
    #pragma unroll
    for (int nt = 0; nt < 4; nt++) {
        int cb = bn * PBNP + wn * 32 + nt * 8 + 2 * q2;
        float b0 = bias[cb], b1 = bias[cb + 1];
        int wi = cb >> 1;
        #pragma unroll
        for (int mt = 0; mt < 4; mt++) {
            int r = g0 + wm * 64 + mt * 16 + rG;
            Cout16[(size_t)r * C_W + wi]       = pack_f16x2(acc[mt][nt][0] + b0, acc[mt][nt][1] + b1);
            Cout16[(size_t)(r + 8) * C_W + wi] = pack_f16x2(acc[mt][nt][2] + b0, acc[mt][nt][3] + b1);
        }
    }
}

// ---------------- GEMM: out-proj (verified R10 v4: 256 thr, 3-stage) ------------
__global__ void __launch_bounds__(256, 2) gemm_out_v4(
    const float* __restrict__ bias, const float* __restrict__ masks,
    const float* __restrict__ x, float* __restrict__ out)
{
    extern __shared__ uint32_t smd[];
    int g0 = blockIdx.x * PBM, bn = blockIdx.y;
    int n = g0 / T_DIM, t0 = g0 % T_DIM;
    const uint32_t* Ab = g_AO16 + (size_t)g0 * C_W;
    const uint32_t* Wb = g_W16 + (size_t)(1536 + bn * PBN) * C_W;

    int tid = threadIdx.x, lane = tid & 31, wid = tid >> 5;
    int wm = wid >> 2, wn = wid & 3, q2 = lane & 3, rG = lane >> 2;
    uint32_t sbase = (uint32_t)__cvta_generic_to_shared(smd);

    float acc[4][4][4];
    #pragma unroll
    for (int a = 0; a < 4; a++)
        #pragma unroll
        for (int b = 0; b < 4; b++)
            #pragma unroll
            for (int c = 0; c < 4; c++) acc[a][b][c] = 0.f;

    int row = tid >> 1, ch = (tid & 1) * 2;

    #pragma unroll
    for (int s = 0; s < 2; s++) {
        uint32_t dA = sbase + s * STAGE32 * 4 + row * 80 + ch * 16;
        uint32_t dB = dA + A_U32 * 4;
        const uint32_t* sA = Ab + (size_t)row * C_W + s * 16 + ch * 4;
        const uint32_t* sB = Wb + (size_t)row * C_W + s * 16 + ch * 4;
        CP_ASYNC16(dA, sA);
        CP_ASYNC16(dA + 16, sA + 4);
        CP_ASYNC16(dB, sB);
        CP_ASYNC16(dB + 16, sB + 4);
        CP_COMMIT();
    }

    for (int kt = 0; kt < NKT; kt++) {
        if (kt + 1 < NKT) CP_WAIT1(); else CP_WAIT0();
        __syncthreads();
        if (kt + 2 < NKT) {
            int st = (kt + 2) % NSTAGE;
            uint32_t dA = sbase + st * STAGE32 * 4 + row * 80 + ch * 16;
            uint32_t dB = dA + A_U32 * 4;
            const uint32_t* sA = Ab + (size_t)row * C_W + (kt + 2) * 16 + ch * 4;
            const uint32_t* sB = Wb + (size_t)row * C_W + (kt + 2) * 16 + ch * 4;
            CP_ASYNC16(dA, sA);
            CP_ASYNC16(dA + 16, sA + 4);
            CP_ASYNC16(dB, sB);
            CP_ASYNC16(dB + 16, sB + 4);
            CP_COMMIT();
        }
        int p = kt % NSTAGE;
        // warp tile 64x32 over 128x128 tile: rB uses wn in 0..3
        {
            uint32_t sA2 = sbase + p * STAGE32 * 4;
            uint32_t sB2 = sbase + (p * STAGE32 + A_U32) * 4;
            int rA = wm * 64 + (lane & 7) + ((lane >> 3) & 1) * 8;
            int cA = ((lane >> 4) & 1) * 16;
            int rB = wn * 32 + (lane & 7) + ((lane >> 4) & 1) * 8;
            int cB = ((lane >> 3) & 1) * 16;
            #pragma unroll
            for (int ks = 0; ks < 2; ks++) {
                uint32_t a[4][4], b[2][4];
                #pragma unroll
                for (int mt = 0; mt < 4; mt++)
                    ldsm_x4(a[mt][0], a[mt][1], a[mt][2], a[mt][3],
                            sA2 + (uint32_t)(rA + mt * 16) * 80 + cA + ks * 32);
                #pragma unroll
                for (int nb = 0; nb < 2; nb++)
                    ldsm_x4(b[nb][0], b[nb][1], b[nb][2], b[nb][3],
                            sB2 + (uint32_t)(rB + nb * 16) * 80 + cB + ks * 32);
                #pragma unroll
                for (int mt = 0; mt < 4; mt++)
                    #pragma unroll
                    for (int nb = 0; nb < 2; nb++) {
                        mma_f16(acc[mt][2 * nb],     a[mt][0], a[mt][1], a[mt][2], a[mt][3],
                                b[nb][0], b[nb][1]);
                        mma_f16(acc[mt][2 * nb + 1], a[mt][0], a[mt][1], a[mt][2], a[mt][3],
                                b[nb][2], b[nb][3]);
                    }
            }
        }
    }

    #pragma unroll
    for (int mt = 0; mt < 4; mt++) {
        int r = wm * 64 + mt * 16 + rG;
        int tA = t0 + r;
        float mkA = masks[(size_t)n * T_DIM + tA];
        float mkB = masks[(size_t)n * T_DIM + tA + 8];
        #pragma unroll
        for (int nt = 0; nt < 4; nt++) {
            int co = bn * PBN + wn * 32 + nt * 8 + 2 * q2;
            #pragma unroll
            for (int cj = 0; cj < 2; cj++) {
                float bb = bias[co + cj];
                size_t iA = ((size_t)(n * C_DIM + co + cj)) * T_DIM + tA;
                out[iA]     = (acc[mt][nt][cj]     + bb) * mkA + x[iA];
                out[iA + 8] = (acc[mt][nt][2 + cj] + bb) * mkB + x[iA + 8];
            }
        }
    }
}

// ---------------- attention (fp16 scratch, fp16 MMA) ---------------------------
__global__ void __launch_bounds__(128) attn_f16(const float* __restrict__ masks)
{
    extern __shared__ uint32_t ash[];
    uint32_t* sQ = ash;
    uint32_t* sK = ash + ABUF2;
    uint32_t* sV = ash + 2 * ABUF2;
    float* skm   = (float*)(ash + 3 * ABUF2);

    int cb = blockIdx.x, h = blockIdx.y;
    int g0 = cb * CHUNK_SZ;
    int n = g0 / T_DIM, t0 = g0 % T_DIM;
    int tid = threadIdx.x, lane = tid & 31, w = tid >> 5;
    int q = lane & 3, rG = lane >> 2;

    if (tid < 64)
        skm[tid] = (masks[(size_t)n * T_DIM + t0 + tid] > 0.f) ? 0.f : NEG_INF;

    {
        int m = tid >> 1;
        int kw0 = (tid & 1) * 16;
        const uint32_t* qp = g_QP16 + (size_t)(g0 + m) * C_W + h * 32 + kw0;
        const uint32_t* kp = g_KP16 + (size_t)(g0 + m) * C_W + h * 32 + kw0;
        #pragma unroll
        for (int i = 0; i < 4; i++) {
            int kw4 = kw0 + i * 4;
            int sb = (kw4 >> 3) * 4;
            int kh = (kw4 >> 2) & 1;
            uint4 u = *(const uint4*)(qp + i * 4);
            sQ[((uint32_t)(sb + 0) * AP2 + m) * 2 + kh] = u.x;
            sQ[((uint32_t)(sb + 1) * AP2 + m) * 2 + kh] = u.y;
            sQ[((uint32_t)(sb + 2) * AP2 + m) * 2 + kh] = u.z;
            sQ[((uint32_t)(sb + 3) * AP2 + m) * 2 + kh] = u.w;
            u = *(const uint4*)(kp + i * 4);
            sK[((uint32_t)(sb + 0) * AP2 + m) * 2 + kh] = u.x;
            sK[((uint32_t)(sb + 1) * AP2 + m) * 2 + kh] = u.y;
            sK[((uint32_t)(sb + 2) * AP2 + m) * 2 + kh] = u.z;
            sK[((uint32_t)(sb + 3) * AP2 + m) * 2 + kh] = u.w;
        }
    }
    {
        int tp = tid >> 2;
        int w0 = (tid & 3) * 8;
        const uint32_t* r0 = g_VP16 + (size_t)(g0 + 2 * tp) * C_W + h * 32 + w0;
        const uint32_t* r1 = r0 + C_W;
        int slot = (tp >> 3) * 4 + (tp & 3);
        int kh = (tp >> 2) & 1;
        uint32_t* dst = sV + ((uint32_t)slot * AP2 + 2 * w0) * 2 + kh;
        #pragma unroll
        for (int half = 0; half < 2; half++) {
            uint4 a = *(const uint4*)(r0 + half * 4);
            uint4 b = *(const uint4*)(r1 + half * 4);
            const uint32_t* aw = (const uint32_t*)&a;
            const uint32_t* bw = (const uint32_t*)&b;
            #pragma unroll
            for (int j = 0; j < 4; j++) {
                dst[(half * 8 + 2 * j) * 2]     = prmt_u32(aw[j], bw[j], 0x5410);
                dst[(half * 8 + 2 * j + 1) * 2] = prmt_u32(aw[j], bw[j], 0x7632);
            }
        }
    }
    __syncthreads();

    int mA = w * 16 + rG;

    float s[8][4];
    #pragma unroll
    for (int nt = 0; nt < 8; nt++)
        #pragma unroll
        for (int j = 0; j < 4; j++) s[nt][j] = 0.f;
    #pragma unroll
    for (int ks = 0; ks < 4; ks++) {
        const uint32_t* Ab = sQ + ((uint32_t)(ks * 4 + q) * AP2) * 2;
        const uint32_t* Bb = sK + ((uint32_t)(ks * 4 + q) * AP2) * 2;
        uint2 aL = *(const uint2*)(Ab + mA * 2);
        uint2 aH = *(const uint2*)(Ab + (mA + 8) * 2);
        #pragma unroll
        for (int nt = 0; nt < 8; nt++) {
            uint2 bb = *(const uint2*)(Bb + (nt * 8 + rG) * 2);
            mma_f16(s[nt], aL.x, aH.x, aL.y, aH.y, bb.x, bb.y);
        }
    }

    const float scale = 0.125f;
    float mxA = -3.4e38f, mxB = -3.4e38f;
    #pragma unroll
    for (int nt = 0; nt < 8; nt++) {
        int c0 = nt * 8 + 2 * q;
        float a0 = skm[c0], a1 = skm[c0 + 1];
        s[nt][0] = s[nt][0] * scale + a0;
        s[nt][1] = s[nt][1] * scale + a1;
        s[nt][2] = s[nt][2] * scale + a0;
        s[nt][3] = s[nt][3] * scale + a1;
        mxA = fmaxf(mxA, fmaxf(s[nt][0], s[nt][1]));
        mxB = fmaxf(mxB, fmaxf(s[nt][2], s[nt][3]));
    }
    mxA = fmaxf(mxA, __shfl_xor_sync(0xffffffffu, mxA, 1));
    mxA = fmaxf(mxA, __shfl_xor_sync(0xffffffffu, mxA, 2));
    mxB = fmaxf(mxB, __shfl_xor_sync(0xffffffffu, mxB, 1));
    mxB = fmaxf(mxB, __shfl_xor_sync(0xffffffffu, mxB, 2));
    float sA = 0.f, sB = 0.f;
    #pragma unroll
    for (int nt = 0; nt < 8; nt++) {
        s[nt][0] = __expf(s[nt][0] - mxA);
        s[nt][1] = __expf(s[nt][1] - mxA);
        s[nt][2] = __expf(s[nt][2] - mxB);
        s[nt][3] = __expf(s[nt][3] - mxB);
        sA += s[nt][0] + s[nt][1];
        sB += s[nt][2] + s[nt][3];
    }
    sA += __shfl_xor_sync(0xffffffffu, sA, 1);
    sA += __shfl_xor_sync(0xffffffffu, sA, 2);
    sB += __shfl_xor_sync(0xffffffffu, sB, 1);
    sB += __shfl_xor_sync(0xffffffffu, sB, 2);
    float iA = 1.f / sA, iB = 1.f / sB;

    #pragma unroll
    for (int nt = 0; nt < 8; nt++) {
        int kw = nt * 4 + q;
        int slot = (kw >> 3) * 4 + (kw & 3);
        int kh = (kw >> 2) & 1;
        sQ[((uint32_t)slot * AP2 + mA) * 2 + kh]     = pack_f16x2(s[nt][0] * iA, s[nt][1] * iA);
        sQ[((uint32_t)slot * AP2 + mA + 8) * 2 + kh] = pack_f16x2(s[nt][2] * iB, s[nt][3] * iB);
    }
    __syncwarp();

    float o[8][4];
    #pragma unroll
    for (int nt = 0; nt < 8; nt++)
        #pragma unroll
        for (int j = 0; j < 4; j++) o[nt][j] = 0.f;
    #pragma unroll
    for (int ks = 0; ks < 4; ks++) {
        const uint32_t* Ab = sQ + ((uint32_t)(ks * 4 + q) * AP2) * 2;
        const uint32_t* Bb = sV + ((uint32_t)(ks * 4 + q) * AP2) * 2;
        uint2 aL = *(const uint2*)(Ab + mA * 2);
        uint2 aH = *(const uint2*)(Ab + (mA + 8) * 2);
        #pragma unroll
        for (int nt = 0; nt < 8; nt++) {
            uint2 bb = *(const uint2*)(Bb + (nt * 8 + rG) * 2);
            mma_f16(o[nt], aL.x, aH.x, aL.y, aH.y, bb.x, bb.y);
        }
    }

    uint32_t* aoA = g_AO16 + (size_t)(g0 + mA) * C_W + h * 32;
    uint32_t* aoB = g_AO16 + (size_t)(g0 + mA + 8) * C_W + h * 32;
    #pragma unroll
    for (int nt = 0; nt < 8; nt++) {
        aoA[nt * 4 + q] = pack_f16x2(o[nt][0], o[nt][1]);
        aoB[nt * 4 + q] = pack_f16x2(o[nt][2], o[nt][3]);
    }
}

// ---------------- InstanceNorm1d over T per (n,c) row ---------------------------
__global__ void __launch_bounds__(256) inorm_kernel(float* __restrict__ out)
{
    __shared__ float red[18];
    int row = blockIdx.x;
    float* p = out + (size_t)row * T_DIM;
    int tid = threadIdx.x;

    float4 v[4];
    float s = 0.f, s2 = 0.f;
    #pragma unroll
    for (int i = 0; i < 4; i++) {
        v[i] = *(const float4*)(p + i * 1024 + tid * 4);
        s  += v[i].x + v[i].y + v[i].z + v[i].w;
        s2 += v[i].x * v[i].x + v[i].y * v[i].y + v[i].z * v[i].z + v[i].w * v[i].w;
    }
    #pragma unroll
    for (int o = 16; o; o >>= 1) {
        s  += __shfl_xor_sync(0xffffffffu, s,  o);
        s2 += __shfl_xor_sync(0xffffffffu, s2, o);
    }
    int warp = tid >> 5, lane = tid & 31;
    if (lane == 0) { red[warp] = s; red[8 + warp] = s2; }
    __syncthreads();
    if (warp == 0) {
        float a  = (lane < 8) ? red[lane]     : 0.f;
        float a2 = (lane < 8) ? red[8 + lane] : 0.f;
        #pragma unroll
        for (int o = 4; o; o >>= 1) {
            a  += __shfl_xor_sync(0xffffffffu, a,  o);
            a2 += __shfl_xor_sync(0xffffffffu, a2, o);
        }
        if (lane == 0) { red[16] = a; red[17] = a2; }
    }
    __syncthreads();
    float mu  = red[16] * (1.f / T_DIM);
    float var = red[17] * (1.f / T_DIM) - mu * mu;
    float rs  = rsqrtf(var + 1e-5f);
    #pragma unroll
    for (int i = 0; i < 4; i++) {
        float4 r;
        r.x = (v[i].x - mu) * rs; r.y = (v[i].y - mu) * rs;
        r.z = (v[i].z - mu) * rs; r.w = (v[i].w - mu) * rs;
        *(float4*)(p + i * 1024 + tid * 4) = r;
    }
}

// ---------------- launch ---------------------------------------------------------
extern "C" void kernel_launch(void* const* d_in, const int* in_sizes, int n_in,
                              void* d_out, int out_size)
{
    const float* x     = (const float*)d_in[0];
    const float* q     = (const float*)d_in[1];
    const float* k     = (const float*)d_in[2];
    const float* v     = (const float*)d_in[3];
    const float* masks = (const float*)d_in[4];
    const float* W_in  = (const float*)d_in[5];
    const float* b_in  = (const float*)d_in[6];
    const float* W_out = (const float*)d_in[7];
    const float* b_out = (const float*)d_in[8];
    float* out = (float*)d_out;

    cudaFuncSetAttribute(attn_f16, cudaFuncAttributeMaxDynamicSharedMemorySize,
                         ASMEM2);
    cudaFuncSetAttribute(gemm_proj_v6, cudaFuncAttributeMaxDynamicSharedMemorySize,
                         PSMEM_BYTES);
    cudaFuncSetAttribute(gemm_out_v4, cudaFuncAttributeMaxDynamicSharedMemorySize,
                         OSMEM_BYTES);

    pack_weights<<<2048, 256>>>(W_in, W_out);

    dim3 gp(NTOK / PBM, C_DIM / PBNP, 3);   // (128, 8, 3)
    gemm_proj_v6<<<gp, 128, PSMEM_BYTES>>>(q, k, v, b_in);

    attn_f16<<<dim3(NTOK / CHUNK_SZ, H_HEADS), 128, ASMEM2>>>(masks);

    dim3 gg(NTOK / PBM, C_DIM / PBN);       // (128, 4)
    gemm_out_v4<<<gg, 256, OSMEM_BYTES>>>(b_out, masks, x, out);

    inorm_kernel<<<N_BATCH * C_DIM, 256>>>(out);
}

// round 14
// speedup vs baseline: 1.0532x; 1.0532x over previous
#include <cuda_runtime.h>
#include <cuda_bf16.h>
#include <cstdint>

#define N_BATCH 4
#define C_DIM   512
#define C_W     256            // C_DIM/2 f16x2 words per row
#define T_DIM   4096
#define NTOK    (N_BATCH * T_DIM)   // 16384
#define H_HEADS 8
#define DH      64
#define CHUNK_SZ 64
#define NEG_INF (-1e9f)

// ---------------- fp16 GEMM tiling ---------------------------------------------
#define PBM 128
#define PBN 128
#define NKT (C_DIM / 32)       // 16 k-tiles of 32
#define WPITCH 20              // u32 per smem row (80 B)
#define A_U32 (128 * WPITCH)   // 2560
#define STAGE32 (2 * A_U32)    // A+B one stage: 5120 u32 (20 KB)
// proj: 2-stage static smem (40 KB, R8-verified); out: 4-stage dynamic (80 KB)
#define OSTAGES 4
#define OSMEM_BYTES (OSTAGES * STAGE32 * 4)  // 81920

// ---------------- fp16 attention tiling ---------------------------------------
#define AP2 68
#define ABUF2 (16 * AP2 * 2)
#define ASMEM2 ((3 * ABUF2 + 64) * 4)

// ---------------- scratch (fp16 packed as u32 words) ---------------------------
__device__ __align__(16) uint32_t g_QP16[(size_t)NTOK * C_W];
__device__ __align__(16) uint32_t g_KP16[(size_t)NTOK * C_W];
__device__ __align__(16) uint32_t g_VP16[(size_t)NTOK * C_W];
__device__ __align__(16) uint32_t g_AO16[(size_t)NTOK * C_W];
__device__ __align__(16) uint32_t g_W16[(size_t)2048 * C_W];   // 0-1535 Win, 1536-2047 Wout

// ---------------- helpers ------------------------------------------------------
__device__ __forceinline__ uint32_t pack_f16x2(float lo, float hi) {
    uint32_t r;
    asm("cvt.rn.f16x2.f32 %0, %1, %2;" : "=r"(r) : "f"(hi), "f"(lo));
    return r;
}

__device__ __forceinline__ uint32_t prmt_u32(uint32_t a, uint32_t b, uint32_t sel) {
    uint32_t r;
    asm("prmt.b32 %0, %1, %2, %3;" : "=r"(r) : "r"(a), "r"(b), "r"(sel));
    return r;
}

__device__ __forceinline__ void mma_f16(float* c,
                                        uint32_t a0, uint32_t a1, uint32_t a2, uint32_t a3,
                                        uint32_t b0, uint32_t b1) {
    asm volatile(
        "mma.sync.aligned.m16n8k16.row.col.f32.f16.f16.f32 "
        "{%0,%1,%2,%3}, {%4,%5,%6,%7}, {%8,%9}, {%0,%1,%2,%3};\n"
        : "+f"(c[0]), "+f"(c[1]), "+f"(c[2]), "+f"(c[3])
        : "r"(a0), "r"(a1), "r"(a2), "r"(a3), "r"(b0), "r"(b1));
}

__device__ __forceinline__ void ldsm_x4(uint32_t& r0, uint32_t& r1, uint32_t& r2,
                                        uint32_t& r3, uint32_t addr) {
    asm volatile("ldmatrix.sync.aligned.m8n8.x4.shared.b16 {%0,%1,%2,%3}, [%4];"
                 : "=r"(r0), "=r"(r1), "=r"(r2), "=r"(r3) : "r"(addr));
}

#define CP_ASYNC16(dst, src) \
    asm volatile("cp.async.cg.shared.global [%0], [%1], 16;" :: "r"(dst), "l"(src))
#define CP_COMMIT() asm volatile("cp.async.commit_group;")
#define CP_WAIT0()  asm volatile("cp.async.wait_group 0;" ::: "memory")
#define CP_WAIT1()  asm volatile("cp.async.wait_group 1;" ::: "memory")
#define CP_WAIT2()  asm volatile("cp.async.wait_group 2;" ::: "memory")

// ---- mma over one BK=32 stage, warp tile 64x64 (4 warps = 2m x 2n), 80B pitch --
__device__ __forceinline__ void mma_tile_64x64(uint32_t sA, uint32_t sB,
                                               float acc[4][8][4],
                                               int wm, int wn, int lane) {
    int rA = wm * 64 + (lane & 7) + ((lane >> 3) & 1) * 8;
    int cA = ((lane >> 4) & 1) * 16;
    int rB = wn * 64 + (lane & 7) + ((lane >> 4) & 1) * 8;
    int cB = ((lane >> 3) & 1) * 16;
    #pragma unroll
    for (int ks = 0; ks < 2; ks++) {
        uint32_t a[4][4], b[4][4];
        #pragma unroll
        for (int mt = 0; mt < 4; mt++)
            ldsm_x4(a[mt][0], a[mt][1], a[mt][2], a[mt][3],
                    sA + (uint32_t)(rA + mt * 16) * 80 + cA + ks * 32);
        #pragma unroll
        for (int nt2 = 0; nt2 < 4; nt2++)
            ldsm_x4(b[nt2][0], b[nt2][1], b[nt2][2], b[nt2][3],
                    sB + (uint32_t)(rB + nt2 * 16) * 80 + cB + ks * 32);
        #pragma unroll
        for (int mt = 0; mt < 4; mt++)
            #pragma unroll
            for (int nt2 = 0; nt2 < 4; nt2++) {
                mma_f16(acc[mt][2 * nt2],     a[mt][0], a[mt][1], a[mt][2], a[mt][3],
                        b[nt2][0], b[nt2][1]);
                mma_f16(acc[mt][2 * nt2 + 1], a[mt][0], a[mt][1], a[mt][2], a[mt][3],
                        b[nt2][2], b[nt2][3]);
            }
    }
}

// ---- mma over one BK=32 stage, warp tile 64x32 (8 warps = 2m x 4n), 80B pitch --
__device__ __forceinline__ void mma_tile_64x32(uint32_t sA, uint32_t sB,
                                               float acc[4][4][4],
                                               int wm, int wn, int lane) {
    int rA = wm * 64 + (lane & 7) + ((lane >> 3) & 1) * 8;
    int cA = ((lane >> 4) & 1) * 16;
    int rB = wn * 32 + (lane & 7) + ((lane >> 4) & 1) * 8;
    int cB = ((lane >> 3) & 1) * 16;
    #pragma unroll
    for (int ks = 0; ks < 2; ks++) {
        uint32_t a[4][4], b[2][4];
        #pragma unroll
        for (int mt = 0; mt < 4; mt++)
            ldsm_x4(a[mt][0], a[mt][1], a[mt][2], a[mt][3],
                    sA + (uint32_t)(rA + mt * 16) * 80 + cA + ks * 32);
        #pragma unroll
        for (int nb = 0; nb < 2; nb++)
            ldsm_x4(b[nb][0], b[nb][1], b[nb][2], b[nb][3],
                    sB + (uint32_t)(rB + nb * 16) * 80 + cB + ks * 32);
        #pragma unroll
        for (int mt = 0; mt < 4; mt++)
            #pragma unroll
            for (int nb = 0; nb < 2; nb++) {
                mma_f16(acc[mt][2 * nb],     a[mt][0], a[mt][1], a[mt][2], a[mt][3],
                        b[nb][0], b[nb][1]);
                mma_f16(acc[mt][2 * nb + 1], a[mt][0], a[mt][1], a[mt][2], a[mt][3],
                        b[nb][2], b[nb][3]);
            }
    }
}

// ---------------- weight pre-pack ----------------------------------------------
__global__ void pack_weights(const float* __restrict__ Win, const float* __restrict__ Wout)
{
    int i = blockIdx.x * 256 + threadIdx.x;
    int row = i >> 8, kw = i & 255;
    const float* src = (row < 1536) ? (Win + (size_t)row * C_DIM + 2 * kw)
                                    : (Wout + (size_t)(row - 1536) * C_DIM + 2 * kw);
    float2 f = *(const float2*)src;
    g_W16[i] = pack_f16x2(f.x, f.y);
}

// ---------------- GEMM: 3 projections (R8/R11-verified config) ------------------
__global__ void __launch_bounds__(128, 2) gemm_proj_v2(
    const float* __restrict__ qin, const float* __restrict__ kin,
    const float* __restrict__ vin, const float* __restrict__ b_in)
{
    __shared__ __align__(16) uint32_t sm[2 * STAGE32];
    int z = blockIdx.z;
    const float* A = (z == 0) ? qin : (z == 1) ? kin : vin;
    uint32_t* Cout16 = (z == 0) ? g_QP16 : (z == 1) ? g_KP16 : g_VP16;
    const float* bias = b_in + z * C_DIM;

    int g0 = blockIdx.x * PBM, bn = blockIdx.y;
    int n = g0 / T_DIM, t0 = g0 % T_DIM;
    const float* Abase = A + (size_t)n * C_DIM * T_DIM + t0;
    const uint32_t* Wb = g_W16 + (size_t)(z * 512 + bn * PBN) * C_W;

    int tid = threadIdx.x, lane = tid & 31, wid = tid >> 5;
    int wm = wid >> 1, wn = wid & 1, q2 = lane & 3, rG = lane >> 2;
    uint32_t sbase = (uint32_t)__cvta_generic_to_shared(sm);

    float acc[4][8][4];
    #pragma unroll
    for (int a = 0; a < 4; a++)
        #pragma unroll
        for (int b = 0; b < 8; b++)
            #pragma unroll
            for (int c = 0; c < 4; c++) acc[a][b][c] = 0.f;

    int m0 = (tid & 31) * 4, kw0 = (tid >> 5) * 4;
    float4 av[8];

    // prologue: stage 0
    {
        int c0 = 2 * kw0;
        #pragma unroll
        for (int cr = 0; cr < 8; cr++)
            av[cr] = *(const float4*)(Abase + (size_t)(c0 + cr) * T_DIM + m0);
        uint32_t d = sbase + A_U32 * 4 + tid * 80;
        const uint32_t* s = Wb + (size_t)tid * C_W;
        #pragma unroll
        for (int ch = 0; ch < 4; ch++) CP_ASYNC16(d + ch * 16, s + ch * 4);
        CP_COMMIT();
        const float* fv = (const float*)av;
        #pragma unroll
        for (int i = 0; i < 4; i++) {
            uint4 u;
            u.x = pack_f16x2(fv[0 + i],  fv[4 + i]);
            u.y = pack_f16x2(fv[8 + i],  fv[12 + i]);
            u.z = pack_f16x2(fv[16 + i], fv[20 + i]);
            u.w = pack_f16x2(fv[24 + i], fv[28 + i]);
            *(uint4*)(sm + (m0 + i) * WPITCH + kw0) = u;
        }
    }
    CP_WAIT0();
    __syncthreads();

    for (int kt = 0; kt < NKT; kt++) {
        int p = kt & 1;
        if (kt + 1 < NKT) {
            int c0 = (kt + 1) * 32 + 2 * kw0;
            #pragma unroll
            for (int cr = 0; cr < 8; cr++)
                av[cr] = *(const float4*)(Abase + (size_t)(c0 + cr) * T_DIM + m0);
            uint32_t d = sbase + ((p ^ 1) * STAGE32 + A_U32) * 4 + tid * 80;
            const uint32_t* s = Wb + (size_t)tid * C_W + (kt + 1) * 16;
            #pragma unroll
            for (int ch = 0; ch < 4; ch++) CP_ASYNC16(d + ch * 16, s + ch * 4);
            CP_COMMIT();
        }
        mma_tile_64x64(sbase + p * STAGE32 * 4, sbase + (p * STAGE32 + A_U32) * 4,
                       acc, wm, wn, lane);
        if (kt + 1 < NKT) {
            uint32_t* buf = sm + (p ^ 1) * STAGE32;
            const float* fv = (const float*)av;
            #pragma unroll
            for (int i = 0; i < 4; i++) {
                uint4 u;
                u.x = pack_f16x2(fv[0 + i],  fv[4 + i]);
                u.y = pack_f16x2(fv[8 + i],  fv[12 + i]);
                u.z = pack_f16x2(fv[16 + i], fv[20 + i]);
                u.w = pack_f16x2(fv[24 + i], fv[28 + i]);
                *(uint4*)(buf + (m0 + i) * WPITCH + kw0) = u;
            }
            CP_WAIT0();
        }
        __syncthreads();
    }

    // epilogue: packed fp16 output [g][cw]
    #pragma unroll
    for (int nt = 0; nt < 8; nt++) {
        int cb = bn * PBN + wn * 64 + nt * 8 + 2 * q2;
        float b0 = bias[cb], b1 = bias[cb + 1];
        int wi = cb >> 1;
        #pragma unroll
        for (int mt = 0; mt < 4; mt++) {
            int r = g0 + wm * 64 + mt * 16 + rG;
            Cout16[(size_t)r * C_W + wi]       = pack_f16x2(acc[mt][nt][0] + b0, acc[mt][nt][1] + b1);
            Cout16[(size_t)(r + 8) * C_W + wi] = pack_f16x2(acc[mt][nt][2] + b0, acc[mt][nt][3] + b1);
        }
    }
}

// ---------------- GEMM: out-proj, 4-stage cp.async pipeline ---------------------
__global__ void __launch_bounds__(256, 2) gemm_out_v6(
    const float* __restrict__ bias, const float* __restrict__ masks,
    const float* __restrict__ x, float* __restrict__ out)
{
    extern __shared__ uint32_t smd[];
    int g0 = blockIdx.x * PBM, bn = blockIdx.y;
    int n = g0 / T_DIM, t0 = g0 % T_DIM;
    const uint32_t* Ab = g_AO16 + (size_t)g0 * C_W;
    const uint32_t* Wb = g_W16 + (size_t)(1536 + bn * PBN) * C_W;

    int tid = threadIdx.x, lane = tid & 31, wid = tid >> 5;
    int wm = wid >> 2, wn = wid & 3, q2 = lane & 3, rG = lane >> 2;
    uint32_t sbase = (uint32_t)__cvta_generic_to_shared(smd);

    float acc[4][4][4];
    #pragma unroll
    for (int a = 0; a < 4; a++)
        #pragma unroll
        for (int b = 0; b < 4; b++)
            #pragma unroll
            for (int c = 0; c < 4; c++) acc[a][b][c] = 0.f;

    int row = tid >> 1, ch = (tid & 1) * 2;

    // prologue: stages 0,1,2
    #pragma unroll
    for (int s = 0; s < 3; s++) {
        uint32_t dA = sbase + s * STAGE32 * 4 + row * 80 + ch * 16;
        uint32_t dB = dA + A_U32 * 4;
        const uint32_t* sA = Ab + (size_t)row * C_W + s * 16 + ch * 4;
        const uint32_t* sB = Wb + (size_t)row * C_W + s * 16 + ch * 4;
        CP_ASYNC16(dA, sA);
        CP_ASYNC16(dA + 16, sA + 4);
        CP_ASYNC16(dB, sB);
        CP_ASYNC16(dB + 16, sB + 4);
        CP_COMMIT();
    }

    for (int kt = 0; kt < NKT; kt++) {
        if (kt + 3 < NKT) CP_WAIT2();
        else if (kt + 2 < NKT) CP_WAIT1();
        else CP_WAIT0();
        __syncthreads();
        if (kt + 3 < NKT) {
            int st = (kt + 3) & 3;
            uint32_t dA = sbase + st * STAGE32 * 4 + row * 80 + ch * 16;
            uint32_t dB = dA + A_U32 * 4;
            const uint32_t* sA = Ab + (size_t)row * C_W + (kt + 3) * 16 + ch * 4;
            const uint32_t* sB = Wb + (size_t)row * C_W + (kt + 3) * 16 + ch * 4;
            CP_ASYNC16(dA, sA);
            CP_ASYNC16(dA + 16, sA + 4);
            CP_ASYNC16(dB, sB);
            CP_ASYNC16(dB + 16, sB + 4);
            CP_COMMIT();
        }
        int p = kt & 3;
        mma_tile_64x32(sbase + p * STAGE32 * 4, sbase + (p * STAGE32 + A_U32) * 4,
                       acc, wm, wn, lane);
    }

    // epilogue: channel-major + mask + residual
    #pragma unroll
    for (int mt = 0; mt < 4; mt++) {
        int r = wm * 64 + mt * 16 + rG;
        int tA = t0 + r;
        float mkA = masks[(size_t)n * T_DIM + tA];
        float mkB = masks[(size_t)n * T_DIM + tA + 8];
        #pragma unroll
        for (int nt = 0; nt < 4; nt++) {
            int co = bn * PBN + wn * 32 + nt * 8 + 2 * q2;
            #pragma unroll
            for (int cj = 0; cj < 2; cj++) {
                float bb = bias[co + cj];
                size_t iA = ((size_t)(n * C_DIM + co + cj)) * T_DIM + tA;
                out[iA]     = (acc[mt][nt][cj]     + bb) * mkA + x[iA];
                out[iA + 8] = (acc[mt][nt][2 + cj] + bb) * mkB + x[iA + 8];
            }
        }
    }
}

// ---------------- attention (fp16 scratch, fp16 MMA) ---------------------------
__global__ void __launch_bounds__(128) attn_f16(const float* __restrict__ masks)
{
    extern __shared__ uint32_t ash[];
    uint32_t* sQ = ash;
    uint32_t* sK = ash + ABUF2;
    uint32_t* sV = ash + 2 * ABUF2;
    float* skm   = (float*)(ash + 3 * ABUF2);

    int cb = blockIdx.x, h = blockIdx.y;
    int g0 = cb * CHUNK_SZ;
    int n = g0 / T_DIM, t0 = g0 % T_DIM;
    int tid = threadIdx.x, lane = tid & 31, w = tid >> 5;
    int q = lane & 3, rG = lane >> 2;

    if (tid < 64)
        skm[tid] = (masks[(size_t)n * T_DIM + t0 + tid] > 0.f) ? 0.f : NEG_INF;

    {
        int m = tid >> 1;
        int kw0 = (tid & 1) * 16;
        const uint32_t* qp = g_QP16 + (size_t)(g0 + m) * C_W + h * 32 + kw0;
        const uint32_t* kp = g_KP16 + (size_t)(g0 + m) * C_W + h * 32 + kw0;
        #pragma unroll
        for (int i = 0; i < 4; i++) {
            int kw4 = kw0 + i * 4;
            int sb = (kw4 >> 3) * 4;
            int kh = (kw4 >> 2) & 1;
            uint4 u = *(const uint4*)(qp + i * 4);
            sQ[((uint32_t)(sb + 0) * AP2 + m) * 2 + kh] = u.x;
            sQ[((uint32_t)(sb + 1) * AP2 + m) * 2 + kh] = u.y;
            sQ[((uint32_t)(sb + 2) * AP2 + m) * 2 + kh] = u.z;
            sQ[((uint32_t)(sb + 3) * AP2 + m) * 2 + kh] = u.w;
            u = *(const uint4*)(kp + i * 4);
            sK[((uint32_t)(sb + 0) * AP2 + m) * 2 + kh] = u.x;
            sK[((uint32_t)(sb + 1) * AP2 + m) * 2 + kh] = u.y;
            sK[((uint32_t)(sb + 2) * AP2 + m) * 2 + kh] = u.z;
            sK[((uint32_t)(sb + 3) * AP2 + m) * 2 + kh] = u.w;
        }
    }
    {
        int tp = tid >> 2;
        int w0 = (tid & 3) * 8;
        const uint32_t* r0 = g_VP16 + (size_t)(g0 + 2 * tp) * C_W + h * 32 + w0;
        const uint32_t* r1 = r0 + C_W;
        int slot = (tp >> 3) * 4 + (tp & 3);
        int kh = (tp >> 2) & 1;
        uint32_t* dst = sV + ((uint32_t)slot * AP2 + 2 * w0) * 2 + kh;
        #pragma unroll
        for (int half = 0; half < 2; half++) {
            uint4 a = *(const uint4*)(r0 + half * 4);
            uint4 b = *(const uint4*)(r1 + half * 4);
            const uint32_t* aw = (const uint32_t*)&a;
            const uint32_t* bw = (const uint32_t*)&b;
            #pragma unroll
            for (int j = 0; j < 4; j++) {
                dst[(half * 8 + 2 * j) * 2]     = prmt_u32(aw[j], bw[j], 0x5410);
                dst[(half * 8 + 2 * j + 1) * 2] = prmt_u32(aw[j], bw[j], 0x7632);
            }
        }
    }
    __syncthreads();

    int mA = w * 16 + rG;

    float s[8][4];
    #pragma unroll
    for (int nt = 0; nt < 8; nt++)
        #pragma unroll
        for (int j = 0; j < 4; j++) s[nt][j] = 0.f;
    #pragma unroll
    for (int ks = 0; ks < 4; ks++) {
        const uint32_t* Ab = sQ + ((uint32_t)(ks * 4 + q) * AP2) * 2;
        const uint32_t* Bb = sK + ((uint32_t)(ks * 4 + q) * AP2) * 2;
        uint2 aL = *(const uint2*)(Ab + mA * 2);
        uint2 aH = *(const uint2*)(Ab + (mA + 8) * 2);
        #pragma unroll
        for (int nt = 0; nt < 8; nt++) {
            uint2 bb = *(const uint2*)(Bb + (nt * 8 + rG) * 2);
            mma_f16(s[nt], aL.x, aH.x, aL.y, aH.y, bb.x, bb.y);
        }
    }

    const float scale = 0.125f;
    float mxA = -3.4e38f, mxB = -3.4e38f;
    #pragma unroll
    for (int nt = 0; nt < 8; nt++) {
        int c0 = nt * 8 + 2 * q;
        float a0 = skm[c0], a1 = skm[c0 + 1];
        s[nt][0] = s[nt][0] * scale + a0;
        s[nt][1] = s[nt][1] * scale + a1;
        s[nt][2] = s[nt][2] * scale + a0;
        s[nt][3] = s[nt][3] * scale + a1;
        mxA = fmaxf(mxA, fmaxf(s[nt][0], s[nt][1]));
        mxB = fmaxf(mxB, fmaxf(s[nt][2], s[nt][3]));
    }
    mxA = fmaxf(mxA, __shfl_xor_sync(0xffffffffu, mxA, 1));
    mxA = fmaxf(mxA, __shfl_xor_sync(0xffffffffu, mxA, 2));
    mxB = fmaxf(mxB, __shfl_xor_sync(0xffffffffu, mxB, 1));
    mxB = fmaxf(mxB, __shfl_xor_sync(0xffffffffu, mxB, 2));
    float sA = 0.f, sB = 0.f;
    #pragma unroll
    for (int nt = 0; nt < 8; nt++) {
        s[nt][0] = __expf(s[nt][0] - mxA);
        s[nt][1] = __expf(s[nt][1] - mxA);
        s[nt][2] = __expf(s[nt][2] - mxB);
        s[nt][3] = __expf(s[nt][3] - mxB);
        sA += s[nt][0] + s[nt][1];
        sB += s[nt][2] + s[nt][3];
    }
    sA += __shfl_xor_sync(0xffffffffu, sA, 1);
    sA += __shfl_xor_sync(0xffffffffu, sA, 2);
    sB += __shfl_xor_sync(0xffffffffu, sB, 1);
    sB += __shfl_xor_sync(0xffffffffu, sB, 2);
    float iA = 1.f / sA, iB = 1.f / sB;

    #pragma unroll
    for (int nt = 0; nt < 8; nt++) {
        int kw = nt * 4 + q;
        int slot = (kw >> 3) * 4 + (kw & 3);
        int kh = (kw >> 2) & 1;
        sQ[((uint32_t)slot * AP2 + mA) * 2 + kh]     = pack_f16x2(s[nt][0] * iA, s[nt][1] * iA);
        sQ[((uint32_t)slot * AP2 + mA + 8) * 2 + kh] = pack_f16x2(s[nt][2] * iB, s[nt][3] * iB);
    }
    __syncwarp();

    float o[8][4];
    #pragma unroll
    for (int nt = 0; nt < 8; nt++)
        #pragma unroll
        for (int j = 0; j < 4; j++) o[nt][j] = 0.f;
    #pragma unroll
    for (int ks = 0; ks < 4; ks++) {
        const uint32_t* Ab = sQ + ((uint32_t)(ks * 4 + q) * AP2) * 2;
        const uint32_t* Bb = sV + ((uint32_t)(ks * 4 + q) * AP2) * 2;
        uint2 aL = *(const uint2*)(Ab + mA * 2);
        uint2 aH = *(const uint2*)(Ab + (mA + 8) * 2);
        #pragma unroll
        for (int nt = 0; nt < 8; nt++) {
            uint2 bb = *(const uint2*)(Bb + (nt * 8 + rG) * 2);
            mma_f16(o[nt], aL.x, aH.x, aL.y, aH.y, bb.x, bb.y);
        }
    }

    uint32_t* aoA = g_AO16 + (size_t)(g0 + mA) * C_W + h * 32;
    uint32_t* aoB = g_AO16 + (size_t)(g0 + mA + 8) * C_W + h * 32;
    #pragma unroll
    for (int nt = 0; nt < 8; nt++) {
        aoA[nt * 4 + q] = pack_f16x2(o[nt][0], o[nt][1]);
        aoB[nt * 4 + q] = pack_f16x2(o[nt][2], o[nt][3]);
    }
}

// ---------------- InstanceNorm1d over T per (n,c) row ---------------------------
__global__ void __launch_bounds__(256) inorm_kernel(float* __restrict__ out)
{
    __shared__ float red[18];
    int row = blockIdx.x;
    float* p = out + (size_t)row * T_DIM;
    int tid = threadIdx.x;

    float4 v[4];
    float s = 0.f, s2 = 0.f;
    #pragma unroll
    for (int i = 0; i < 4; i++) {
        v[i] = *(const float4*)(p + i * 1024 + tid * 4);
        s  += v[i].x + v[i].y + v[i].z + v[i].w;
        s2 += v[i].x * v[i].x + v[i].y * v[i].y + v[i].z * v[i].z + v[i].w * v[i].w;
    }
    #pragma unroll
    for (int o = 16; o; o >>= 1) {
        s  += __shfl_xor_sync(0xffffffffu, s,  o);
        s2 += __shfl_xor_sync(0xffffffffu, s2, o);
    }
    int warp = tid >> 5, lane = tid & 31;
    if (lane == 0) { red[warp] = s; red[8 + warp] = s2; }
    __syncthreads();
    if (warp == 0) {
        float a  = (lane < 8) ? red[lane]     : 0.f;
        float a2 = (lane < 8) ? red[8 + lane] : 0.f;
        #pragma unroll
        for (int o = 4; o; o >>= 1) {
            a  += __shfl_xor_sync(0xffffffffu, a,  o);
            a2 += __shfl_xor_sync(0xffffffffu, a2, o);
        }
        if (lane == 0) { red[16] = a; red[17] = a2; }
    }
    __syncthreads();
    float mu  = red[16] * (1.f / T_DIM);
    float var = red[17] * (1.f / T_DIM) - mu * mu;
    float rs  = rsqrtf(var + 1e-5f);
    #pragma unroll
    for (int i = 0; i < 4; i++) {
        float4 r;
        r.x = (v[i].x - mu) * rs; r.y = (v[i].y - mu) * rs;
        r.z = (v[i].z - mu) * rs; r.w = (v[i].w - mu) * rs;
        *(float4*)(p + i * 1024 + tid * 4) = r;
    }
}

// ---------------- launch ---------------------------------------------------------
extern "C" void kernel_launch(void* const* d_in, const int* in_sizes, int n_in,
                              void* d_out, int out_size)
{
    const float* x     = (const float*)d_in[0];
    const float* q     = (const float*)d_in[1];
    const float* k     = (const float*)d_in[2];
    const float* v     = (const float*)d_in[3];
    const float* masks = (const float*)d_in[4];
    const float* W_in  = (const float*)d_in[5];
    const float* b_in  = (const float*)d_in[6];
    const float* W_out = (const float*)d_in[7];
    const float* b_out = (const float*)d_in[8];
    float* out = (float*)d_out;

    cudaFuncSetAttribute(attn_f16, cudaFuncAttributeMaxDynamicSharedMemorySize,
                         ASMEM2);
    cudaFuncSetAttribute(gemm_out_v6, cudaFuncAttributeMaxDynamicSharedMemorySize,
                         OSMEM_BYTES);

    pack_weights<<<2048, 256>>>(W_in, W_out);

    dim3 gp(NTOK / PBM, C_DIM / PBN, 3);   // (128, 4, 3)
    gemm_proj_v2<<<gp, 128>>>(q, k, v, b_in);

    attn_f16<<<dim3(NTOK / CHUNK_SZ, H_HEADS), 128, ASMEM2>>>(masks);

    dim3 gg(NTOK / PBM, C_DIM / PBN);      // (128, 4)
    gemm_out_v6<<<gg, 256, OSMEM_BYTES>>>(b_out, masks, x, out);

    inorm_kernel<<<N_BATCH * C_DIM, 256>>>(out);
}

// round 15
// speedup vs baseline: 1.0737x; 1.0195x over previous
#include <cuda_runtime.h>
#include <cuda_bf16.h>
#include <cstdint>

#define N_BATCH 4
#define C_DIM   512
#define C_W     256            // C_DIM/2 f16x2 words per row
#define T_DIM   4096
#define NTOK    (N_BATCH * T_DIM)   // 16384
#define H_HEADS 8
#define DH      64
#define CHUNK_SZ 64
#define NEG_INF (-1e9f)

// ---------------- proj GEMM tiling (R8/R11-verified: 128x128, 2-stage) ----------
#define PBM 128
#define PBN 128
#define NKT (C_DIM / 32)       // 16 k-tiles of 32
#define WPITCH 20              // u32 per smem row (80 B)
#define A_U32 (128 * WPITCH)   // 2560
#define STAGE32 (2 * A_U32)    // A+B one stage: 5120 u32 (20 KB)

// ---------------- out GEMM tiling (128x64, 3-stage, 32x32 warp tiles) -----------
#define OBN 64
#define OB_U32 (64 * WPITCH)            // 1280
#define OSTG (A_U32 + OB_U32)           // 3840 u32 (15 KB)
#define NSTAGE 3
#define OSMEM_BYTES (NSTAGE * OSTG * 4) // 46080

// ---------------- fp16 attention tiling ---------------------------------------
#define AP2 68
#define ABUF2 (16 * AP2 * 2)
#define ASMEM2 ((3 * ABUF2 + 64) * 4)

// ---------------- scratch (fp16 packed as u32 words) ---------------------------
__device__ __align__(16) uint32_t g_QP16[(size_t)NTOK * C_W];
__device__ __align__(16) uint32_t g_KP16[(size_t)NTOK * C_W];
__device__ __align__(16) uint32_t g_VP16[(size_t)NTOK * C_W];
__device__ __align__(16) uint32_t g_AO16[(size_t)NTOK * C_W];
__device__ __align__(16) uint32_t g_W16[(size_t)2048 * C_W];   // 0-1535 Win, 1536-2047 Wout

// ---------------- helpers ------------------------------------------------------
__device__ __forceinline__ uint32_t pack_f16x2(float lo, float hi) {
    uint32_t r;
    asm("cvt.rn.f16x2.f32 %0, %1, %2;" : "=r"(r) : "f"(hi), "f"(lo));
    return r;
}

__device__ __forceinline__ uint32_t prmt_u32(uint32_t a, uint32_t b, uint32_t sel) {
    uint32_t r;
    asm("prmt.b32 %0, %1, %2, %3;" : "=r"(r) : "r"(a), "r"(b), "r"(sel));
    return r;
}

__device__ __forceinline__ void mma_f16(float* c,
                                        uint32_t a0, uint32_t a1, uint32_t a2, uint32_t a3,
                                        uint32_t b0, uint32_t b1) {
    asm volatile(
        "mma.sync.aligned.m16n8k16.row.col.f32.f16.f16.f32 "
        "{%0,%1,%2,%3}, {%4,%5,%6,%7}, {%8,%9}, {%0,%1,%2,%3};\n"
        : "+f"(c[0]), "+f"(c[1]), "+f"(c[2]), "+f"(c[3])
        : "r"(a0), "r"(a1), "r"(a2), "r"(a3), "r"(b0), "r"(b1));
}

__device__ __forceinline__ void ldsm_x4(uint32_t& r0, uint32_t& r1, uint32_t& r2,
                                        uint32_t& r3, uint32_t addr) {
    asm volatile("ldmatrix.sync.aligned.m8n8.x4.shared.b16 {%0,%1,%2,%3}, [%4];"
                 : "=r"(r0), "=r"(r1), "=r"(r2), "=r"(r3) : "r"(addr));
}

#define CP_ASYNC16(dst, src) \
    asm volatile("cp.async.cg.shared.global [%0], [%1], 16;" :: "r"(dst), "l"(src))
#define CP_COMMIT() asm volatile("cp.async.commit_group;")
#define CP_WAIT0()  asm volatile("cp.async.wait_group 0;" ::: "memory")
#define CP_WAIT1()  asm volatile("cp.async.wait_group 1;" ::: "memory")

// ---- mma over one BK=32 stage, warp tile 64x64 (proj: 4 warps = 2m x 2n) -------
__device__ __forceinline__ void mma_tile_64x64(uint32_t sA, uint32_t sB,
                                               float acc[4][8][4],
                                               int wm, int wn, int lane) {
    int rA = wm * 64 + (lane & 7) + ((lane >> 3) & 1) * 8;
    int cA = ((lane >> 4) & 1) * 16;
    int rB = wn * 64 + (lane & 7) + ((lane >> 4) & 1) * 8;
    int cB = ((lane >> 3) & 1) * 16;
    #pragma unroll
    for (int ks = 0; ks < 2; ks++) {
        uint32_t a[4][4], b[4][4];
        #pragma unroll
        for (int mt = 0; mt < 4; mt++)
            ldsm_x4(a[mt][0], a[mt][1], a[mt][2], a[mt][3],
                    sA + (uint32_t)(rA + mt * 16) * 80 + cA + ks * 32);
        #pragma unroll
        for (int nt2 = 0; nt2 < 4; nt2++)
            ldsm_x4(b[nt2][0], b[nt2][1], b[nt2][2], b[nt2][3],
                    sB + (uint32_t)(rB + nt2 * 16) * 80 + cB + ks * 32);
        #pragma unroll
        for (int mt = 0; mt < 4; mt++)
            #pragma unroll
            for (int nt2 = 0; nt2 < 4; nt2++) {
                mma_f16(acc[mt][2 * nt2],     a[mt][0], a[mt][1], a[mt][2], a[mt][3],
                        b[nt2][0], b[nt2][1]);
                mma_f16(acc[mt][2 * nt2 + 1], a[mt][0], a[mt][1], a[mt][2], a[mt][3],
                        b[nt2][2], b[nt2][3]);
            }
    }
}

// ---- mma over one BK=32 stage, warp tile 32x32 (out: 8 warps = 4m x 2n) --------
__device__ __forceinline__ void mma_tile_32x32(uint32_t sA, uint32_t sB,
                                               float acc[2][4][4],
                                               int wm, int wn, int lane) {
    int rA = wm * 32 + (lane & 7) + ((lane >> 3) & 1) * 8;
    int cA = ((lane >> 4) & 1) * 16;
    int rB = wn * 32 + (lane & 7) + ((lane >> 4) & 1) * 8;
    int cB = ((lane >> 3) & 1) * 16;
    #pragma unroll
    for (int ks = 0; ks < 2; ks++) {
        uint32_t a[2][4], b[2][4];
        #pragma unroll
        for (int mt = 0; mt < 2; mt++)
            ldsm_x4(a[mt][0], a[mt][1], a[mt][2], a[mt][3],
                    sA + (uint32_t)(rA + mt * 16) * 80 + cA + ks * 32);
        #pragma unroll
        for (int nb = 0; nb < 2; nb++)
            ldsm_x4(b[nb][0], b[nb][1], b[nb][2], b[nb][3],
                    sB + (uint32_t)(rB + nb * 16) * 80 + cB + ks * 32);
        #pragma unroll
        for (int mt = 0; mt < 2; mt++)
            #pragma unroll
            for (int nb = 0; nb < 2; nb++) {
                mma_f16(acc[mt][2 * nb],     a[mt][0], a[mt][1], a[mt][2], a[mt][3],
                        b[nb][0], b[nb][1]);
                mma_f16(acc[mt][2 * nb + 1], a[mt][0], a[mt][1], a[mt][2], a[mt][3],
                        b[nb][2], b[nb][3]);
            }
    }
}

// ---------------- weight pre-pack ----------------------------------------------
__global__ void pack_weights(const float* __restrict__ Win, const float* __restrict__ Wout)
{
    int i = blockIdx.x * 256 + threadIdx.x;
    int row = i >> 8, kw = i & 255;
    const float* src = (row < 1536) ? (Win + (size_t)row * C_DIM + 2 * kw)
                                    : (Wout + (size_t)(row - 1536) * C_DIM + 2 * kw);
    float2 f = *(const float2*)src;
    g_W16[i] = pack_f16x2(f.x, f.y);
}

// ---------------- GEMM: 3 projections (R8/R11-verified config) ------------------
__global__ void __launch_bounds__(128, 2) gemm_proj_v2(
    const float* __restrict__ qin, const float* __restrict__ kin,
    const float* __restrict__ vin, const float* __restrict__ b_in)
{
    __shared__ __align__(16) uint32_t sm[2 * STAGE32];
    int z = blockIdx.z;
    const float* A = (z == 0) ? qin : (z == 1) ? kin : vin;
    uint32_t* Cout16 = (z == 0) ? g_QP16 : (z == 1) ? g_KP16 : g_VP16;
    const float* bias = b_in + z * C_DIM;

    int g0 = blockIdx.x * PBM, bn = blockIdx.y;
    int n = g0 / T_DIM, t0 = g0 % T_DIM;
    const float* Abase = A + (size_t)n * C_DIM * T_DIM + t0;
    const uint32_t* Wb = g_W16 + (size_t)(z * 512 + bn * PBN) * C_W;

    int tid = threadIdx.x, lane = tid & 31, wid = tid >> 5;
    int wm = wid >> 1, wn = wid & 1, q2 = lane & 3, rG = lane >> 2;
    uint32_t sbase = (uint32_t)__cvta_generic_to_shared(sm);

    float acc[4][8][4];
    #pragma unroll
    for (int a = 0; a < 4; a++)
        #pragma unroll
        for (int b = 0; b < 8; b++)
            #pragma unroll
            for (int c = 0; c < 4; c++) acc[a][b][c] = 0.f;

    int m0 = (tid & 31) * 4, kw0 = (tid >> 5) * 4;
    float4 av[8];

    // prologue: stage 0
    {
        int c0 = 2 * kw0;
        #pragma unroll
        for (int cr = 0; cr < 8; cr++)
            av[cr] = *(const float4*)(Abase + (size_t)(c0 + cr) * T_DIM + m0);
        uint32_t d = sbase + A_U32 * 4 + tid * 80;
        const uint32_t* s = Wb + (size_t)tid * C_W;
        #pragma unroll
        for (int ch = 0; ch < 4; ch++) CP_ASYNC16(d + ch * 16, s + ch * 4);
        CP_COMMIT();
        const float* fv = (const float*)av;
        #pragma unroll
        for (int i = 0; i < 4; i++) {
            uint4 u;
            u.x = pack_f16x2(fv[0 + i],  fv[4 + i]);
            u.y = pack_f16x2(fv[8 + i],  fv[12 + i]);
            u.z = pack_f16x2(fv[16 + i], fv[20 + i]);
            u.w = pack_f16x2(fv[24 + i], fv[28 + i]);
            *(uint4*)(sm + (m0 + i) * WPITCH + kw0) = u;
        }
    }
    CP_WAIT0();
    __syncthreads();

    for (int kt = 0; kt < NKT; kt++) {
        int p = kt & 1;
        if (kt + 1 < NKT) {
            int c0 = (kt + 1) * 32 + 2 * kw0;
            #pragma unroll
            for (int cr = 0; cr < 8; cr++)
                av[cr] = *(const float4*)(Abase + (size_t)(c0 + cr) * T_DIM + m0);
            uint32_t d = sbase + ((p ^ 1) * STAGE32 + A_U32) * 4 + tid * 80;
            const uint32_t* s = Wb + (size_t)tid * C_W + (kt + 1) * 16;
            #pragma unroll
            for (int ch = 0; ch < 4; ch++) CP_ASYNC16(d + ch * 16, s + ch * 4);
            CP_COMMIT();
        }
        mma_tile_64x64(sbase + p * STAGE32 * 4, sbase + (p * STAGE32 + A_U32) * 4,
                       acc, wm, wn, lane);
        if (kt + 1 < NKT) {
            uint32_t* buf = sm + (p ^ 1) * STAGE32;
            const float* fv = (const float*)av;
            #pragma unroll
            for (int i = 0; i < 4; i++) {
                uint4 u;
                u.x = pack_f16x2(fv[0 + i],  fv[4 + i]);
                u.y = pack_f16x2(fv[8 + i],  fv[12 + i]);
                u.z = pack_f16x2(fv[16 + i], fv[20 + i]);
                u.w = pack_f16x2(fv[24 + i], fv[28 + i]);
                *(uint4*)(buf + (m0 + i) * WPITCH + kw0) = u;
            }
            CP_WAIT0();
        }
        __syncthreads();
    }

    // epilogue: packed fp16 output [g][cw]
    #pragma unroll
    for (int nt = 0; nt < 8; nt++) {
        int cb = bn * PBN + wn * 64 + nt * 8 + 2 * q2;
        float b0 = bias[cb], b1 = bias[cb + 1];
        int wi = cb >> 1;
        #pragma unroll
        for (int mt = 0; mt < 4; mt++) {
            int r = g0 + wm * 64 + mt * 16 + rG;
            Cout16[(size_t)r * C_W + wi]       = pack_f16x2(acc[mt][nt][0] + b0, acc[mt][nt][1] + b1);
            Cout16[(size_t)(r + 8) * C_W + wi] = pack_f16x2(acc[mt][nt][2] + b0, acc[mt][nt][3] + b1);
        }
    }
}

// ---------------- GEMM: out-proj, 128x64 tile, 32x32 warps, 3 CTAs/SM -----------
__global__ void __launch_bounds__(256, 3) gemm_out_v7(
    const float* __restrict__ bias, const float* __restrict__ masks,
    const float* __restrict__ x, float* __restrict__ out)
{
    extern __shared__ uint32_t smd[];
    int g0 = blockIdx.x * PBM, bn = blockIdx.y;
    int n = g0 / T_DIM, t0 = g0 % T_DIM;
    const uint32_t* Ab = g_AO16 + (size_t)g0 * C_W;
    const uint32_t* Wb = g_W16 + (size_t)(1536 + bn * OBN) * C_W;

    int tid = threadIdx.x, lane = tid & 31, wid = tid >> 5;
    int wm = wid >> 1, wn = wid & 1, q2 = lane & 3, rG = lane >> 2;
    uint32_t sbase = (uint32_t)__cvta_generic_to_shared(smd);

    float acc[2][4][4];
    #pragma unroll
    for (int a = 0; a < 2; a++)
        #pragma unroll
        for (int b = 0; b < 4; b++)
            #pragma unroll
            for (int c = 0; c < 4; c++) acc[a][b][c] = 0.f;

    int arow = tid >> 1, ach = (tid & 1) * 2;   // A: 2 cp.async / thread
    int brow = tid >> 2, bch = tid & 3;         // B: 1 cp.async / thread

    // prologue: stages 0 and 1
    #pragma unroll
    for (int s = 0; s < 2; s++) {
        uint32_t dA = sbase + s * OSTG * 4 + arow * 80 + ach * 16;
        const uint32_t* sA = Ab + (size_t)arow * C_W + s * 16 + ach * 4;
        CP_ASYNC16(dA, sA);
        CP_ASYNC16(dA + 16, sA + 4);
        uint32_t dB = sbase + (s * OSTG + A_U32) * 4 + brow * 80 + bch * 16;
        const uint32_t* sB = Wb + (size_t)brow * C_W + s * 16 + bch * 4;
        CP_ASYNC16(dB, sB);
        CP_COMMIT();
    }

    for (int kt = 0; kt < NKT; kt++) {
        if (kt + 1 < NKT) CP_WAIT1(); else CP_WAIT0();
        __syncthreads();
        if (kt + 2 < NKT) {
            int st = (kt + 2) % NSTAGE;
            uint32_t dA = sbase + st * OSTG * 4 + arow * 80 + ach * 16;
            const uint32_t* sA = Ab + (size_t)arow * C_W + (kt + 2) * 16 + ach * 4;
            CP_ASYNC16(dA, sA);
            CP_ASYNC16(dA + 16, sA + 4);
            uint32_t dB = sbase + (st * OSTG + A_U32) * 4 + brow * 80 + bch * 16;
            const uint32_t* sB = Wb + (size_t)brow * C_W + (kt + 2) * 16 + bch * 4;
            CP_ASYNC16(dB, sB);
            CP_COMMIT();
        }
        int p = kt % NSTAGE;
        mma_tile_32x32(sbase + p * OSTG * 4, sbase + (p * OSTG + A_U32) * 4,
                       acc, wm, wn, lane);
    }

    // epilogue: channel-major + mask + residual
    #pragma unroll
    for (int mt = 0; mt < 2; mt++) {
        int r = wm * 32 + mt * 16 + rG;
        int tA = t0 + r;
        float mkA = masks[(size_t)n * T_DIM + tA];
        float mkB = masks[(size_t)n * T_DIM + tA + 8];
        #pragma unroll
        for (int nt = 0; nt < 4; nt++) {
            int co = bn * OBN + wn * 32 + nt * 8 + 2 * q2;
            #pragma unroll
            for (int cj = 0; cj < 2; cj++) {
                float bb = bias[co + cj];
                size_t iA = ((size_t)(n * C_DIM + co + cj)) * T_DIM + tA;
                out[iA]     = (acc[mt][nt][cj]     + bb) * mkA + x[iA];
                out[iA + 8] = (acc[mt][nt][2 + cj] + bb) * mkB + x[iA + 8];
            }
        }
    }
}

// ---------------- attention (fp16 scratch, fp16 MMA) ---------------------------
__global__ void __launch_bounds__(128) attn_f16(const float* __restrict__ masks)
{
    extern __shared__ uint32_t ash[];
    uint32_t* sQ = ash;
    uint32_t* sK = ash + ABUF2;
    uint32_t* sV = ash + 2 * ABUF2;
    float* skm   = (float*)(ash + 3 * ABUF2);

    int cb = blockIdx.x, h = blockIdx.y;
    int g0 = cb * CHUNK_SZ;
    int n = g0 / T_DIM, t0 = g0 % T_DIM;
    int tid = threadIdx.x, lane = tid & 31, w = tid >> 5;
    int q = lane & 3, rG = lane >> 2;

    if (tid < 64)
        skm[tid] = (masks[(size_t)n * T_DIM + t0 + tid] > 0.f) ? 0.f : NEG_INF;

    {
        int m = tid >> 1;
        int kw0 = (tid & 1) * 16;
        const uint32_t* qp = g_QP16 + (size_t)(g0 + m) * C_W + h * 32 + kw0;
        const uint32_t* kp = g_KP16 + (size_t)(g0 + m) * C_W + h * 32 + kw0;
        #pragma unroll
        for (int i = 0; i < 4; i++) {
            int kw4 = kw0 + i * 4;
            int sb = (kw4 >> 3) * 4;
            int kh = (kw4 >> 2) & 1;
            uint4 u = *(const uint4*)(qp + i * 4);
            sQ[((uint32_t)(sb + 0) * AP2 + m) * 2 + kh] = u.x;
            sQ[((uint32_t)(sb + 1) * AP2 + m) * 2 + kh] = u.y;
            sQ[((uint32_t)(sb + 2) * AP2 + m) * 2 + kh] = u.z;
            sQ[((uint32_t)(sb + 3) * AP2 + m) * 2 + kh] = u.w;
            u = *(const uint4*)(kp + i * 4);
            sK[((uint32_t)(sb + 0) * AP2 + m) * 2 + kh] = u.x;
            sK[((uint32_t)(sb + 1) * AP2 + m) * 2 + kh] = u.y;
            sK[((uint32_t)(sb + 2) * AP2 + m) * 2 + kh] = u.z;
            sK[((uint32_t)(sb + 3) * AP2 + m) * 2 + kh] = u.w;
        }
    }
    {
        int tp = tid >> 2;
        int w0 = (tid & 3) * 8;
        const uint32_t* r0 = g_VP16 + (size_t)(g0 + 2 * tp) * C_W + h * 32 + w0;
        const uint32_t* r1 = r0 + C_W;
        int slot = (tp >> 3) * 4 + (tp & 3);
        int kh = (tp >> 2) & 1;
        uint32_t* dst = sV + ((uint32_t)slot * AP2 + 2 * w0) * 2 + kh;
        #pragma unroll
        for (int half = 0; half < 2; half++) {
            uint4 a = *(const uint4*)(r0 + half * 4);
            uint4 b = *(const uint4*)(r1 + half * 4);
            const uint32_t* aw = (const uint32_t*)&a;
            const uint32_t* bw = (const uint32_t*)&b;
            #pragma unroll
            for (int j = 0; j < 4; j++) {
                dst[(half * 8 + 2 * j) * 2]     = prmt_u32(aw[j], bw[j], 0x5410);
                dst[(half * 8 + 2 * j + 1) * 2] = prmt_u32(aw[j], bw[j], 0x7632);
            }
        }
    }
    __syncthreads();

    int mA = w * 16 + rG;

    float s[8][4];
    #pragma unroll
    for (int nt = 0; nt < 8; nt++)
        #pragma unroll
        for (int j = 0; j < 4; j++) s[nt][j] = 0.f;
    #pragma unroll
    for (int ks = 0; ks < 4; ks++) {
        const uint32_t* Ab = sQ + ((uint32_t)(ks * 4 + q) * AP2) * 2;
        const uint32_t* Bb = sK + ((uint32_t)(ks * 4 + q) * AP2) * 2;
        uint2 aL = *(const uint2*)(Ab + mA * 2);
        uint2 aH = *(const uint2*)(Ab + (mA + 8) * 2);
        #pragma unroll
        for (int nt = 0; nt < 8; nt++) {
            uint2 bb = *(const uint2*)(Bb + (nt * 8 + rG) * 2);
            mma_f16(s[nt], aL.x, aH.x, aL.y, aH.y, bb.x, bb.y);
        }
    }

    const float scale = 0.125f;
    float mxA = -3.4e38f, mxB = -3.4e38f;
    #pragma unroll
    for (int nt = 0; nt < 8; nt++) {
        int c0 = nt * 8 + 2 * q;
        float a0 = skm[c0], a1 = skm[c0 + 1];
        s[nt][0] = s[nt][0] * scale + a0;
        s[nt][1] = s[nt][1] * scale + a1;
        s[nt][2] = s[nt][2] * scale + a0;
        s[nt][3] = s[nt][3] * scale + a1;
        mxA = fmaxf(mxA, fmaxf(s[nt][0], s[nt][1]));
        mxB = fmaxf(mxB, fmaxf(s[nt][2], s[nt][3]));
    }
    mxA = fmaxf(mxA, __shfl_xor_sync(0xffffffffu, mxA, 1));
    mxA = fmaxf(mxA, __shfl_xor_sync(0xffffffffu, mxA, 2));
    mxB = fmaxf(mxB, __shfl_xor_sync(0xffffffffu, mxB, 1));
    mxB = fmaxf(mxB, __shfl_xor_sync(0xffffffffu, mxB, 2));
    float sA = 0.f, sB = 0.f;
    #pragma unroll
    for (int nt = 0; nt < 8; nt++) {
        s[nt][0] = __expf(s[nt][0] - mxA);
        s[nt][1] = __expf(s[nt][1] - mxA);
        s[nt][2] = __expf(s[nt][2] - mxB);
        s[nt][3] = __expf(s[nt][3] - mxB);
        sA += s[nt][0] + s[nt][1];
        sB += s[nt][2] + s[nt][3];
    }
    sA += __shfl_xor_sync(0xffffffffu, sA, 1);
    sA += __shfl_xor_sync(0xffffffffu, sA, 2);
    sB += __shfl_xor_sync(0xffffffffu, sB, 1);
    sB += __shfl_xor_sync(0xffffffffu, sB, 2);
    float iA = 1.f / sA, iB = 1.f / sB;

    #pragma unroll
    for (int nt = 0; nt < 8; nt++) {
        int kw = nt * 4 + q;
        int slot = (kw >> 3) * 4 + (kw & 3);
        int kh = (kw >> 2) & 1;
        sQ[((uint32_t)slot * AP2 + mA) * 2 + kh]     = pack_f16x2(s[nt][0] * iA, s[nt][1] * iA);
        sQ[((uint32_t)slot * AP2 + mA + 8) * 2 + kh] = pack_f16x2(s[nt][2] * iB, s[nt][3] * iB);
    }
    __syncwarp();

    float o[8][4];
    #pragma unroll
    for (int nt = 0; nt < 8; nt++)
        #pragma unroll
        for (int j = 0; j < 4; j++) o[nt][j] = 0.f;
    #pragma unroll
    for (int ks = 0; ks < 4; ks++) {
        const uint32_t* Ab = sQ + ((uint32_t)(ks * 4 + q) * AP2) * 2;
        const uint32_t* Bb = sV + ((uint32_t)(ks * 4 + q) * AP2) * 2;
        uint2 aL = *(const uint2*)(Ab + mA * 2);
        uint2 aH = *(const uint2*)(Ab + (mA + 8) * 2);
        #pragma unroll
        for (int nt = 0; nt < 8; nt++) {
            uint2 bb = *(const uint2*)(Bb + (nt * 8 + rG) * 2);
            mma_f16(o[nt], aL.x, aH.x, aL.y, aH.y, bb.x, bb.y);
        }
    }

    uint32_t* aoA = g_AO16 + (size_t)(g0 + mA) * C_W + h * 32;
    uint32_t* aoB = g_AO16 + (size_t)(g0 + mA + 8) * C_W + h * 32;
    #pragma unroll
    for (int nt = 0; nt < 8; nt++) {
        aoA[nt * 4 + q] = pack_f16x2(o[nt][0], o[nt][1]);
        aoB[nt * 4 + q] = pack_f16x2(o[nt][2], o[nt][3]);
    }
}

// ---------------- InstanceNorm1d over T per (n,c) row ---------------------------
__global__ void __launch_bounds__(256) inorm_kernel(float* __restrict__ out)
{
    __shared__ float red[18];
    int row = blockIdx.x;
    float* p = out + (size_t)row * T_DIM;
    int tid = threadIdx.x;

    float4 v[4];
    float s = 0.f, s2 = 0.f;
    #pragma unroll
    for (int i = 0; i < 4; i++) {
        v[i] = *(const float4*)(p + i * 1024 + tid * 4);
        s  += v[i].x + v[i].y + v[i].z + v[i].w;
        s2 += v[i].x * v[i].x + v[i].y * v[i].y + v[i].z * v[i].z + v[i].w * v[i].w;
    }
    #pragma unroll
    for (int o = 16; o; o >>= 1) {
        s  += __shfl_xor_sync(0xffffffffu, s,  o);
        s2 += __shfl_xor_sync(0xffffffffu, s2, o);
    }
    int warp = tid >> 5, lane = tid & 31;
    if (lane == 0) { red[warp] = s; red[8 + warp] = s2; }
    __syncthreads();
    if (warp == 0) {
        float a  = (lane < 8) ? red[lane]     : 0.f;
        float a2 = (lane < 8) ? red[8 + lane] : 0.f;
        #pragma unroll
        for (int o = 4; o; o >>= 1) {
            a  += __shfl_xor_sync(0xffffffffu, a,  o);
            a2 += __shfl_xor_sync(0xffffffffu, a2, o);
        }
        if (lane == 0) { red[16] = a; red[17] = a2; }
    }
    __syncthreads();
    float mu  = red[16] * (1.f / T_DIM);
    float var = red[17] * (1.f / T_DIM) - mu * mu;
    float rs  = rsqrtf(var + 1e-5f);
    #pragma unroll
    for (int i = 0; i < 4; i++) {
        float4 r;
        r.x = (v[i].x - mu) * rs; r.y = (v[i].y - mu) * rs;
        r.z = (v[i].z - mu) * rs; r.w = (v[i].w - mu) * rs;
        *(float4*)(p + i * 1024 + tid * 4) = r;
    }
}

// ---------------- launch ---------------------------------------------------------
extern "C" void kernel_launch(void* const* d_in, const int* in_sizes, int n_in,
                              void* d_out, int out_size)
{
    const float* x     = (const float*)d_in[0];
    const float* q     = (const float*)d_in[1];
    const float* k     = (const float*)d_in[2];
    const float* v     = (const float*)d_in[3];
    const float* masks = (const float*)d_in[4];
    const float* W_in  = (const float*)d_in[5];
    const float* b_in  = (const float*)d_in[6];
    const float* W_out = (const float*)d_in[7];
    const float* b_out = (const float*)d_in[8];
    float* out = (float*)d_out;

    cudaFuncSetAttribute(attn_f16, cudaFuncAttributeMaxDynamicSharedMemorySize,
                         ASMEM2);
    cudaFuncSetAttribute(gemm_out_v7, cudaFuncAttributeMaxDynamicSharedMemorySize,
                         OSMEM_BYTES);

    pack_weights<<<2048, 256>>>(W_in, W_out);

    dim3 gp(NTOK / PBM, C_DIM / PBN, 3);   // (128, 4, 3)
    gemm_proj_v2<<<gp, 128>>>(q, k, v, b_in);

    attn_f16<<<dim3(NTOK / CHUNK_SZ, H_HEADS), 128, ASMEM2>>>(masks);

    dim3 gg(NTOK / PBM, C_DIM / OBN);      // (128, 8)
    gemm_out_v7<<<gg, 256, OSMEM_BYTES>>>(b_out, masks, x, out);

    inorm_kernel<<<N_BATCH * C_DIM, 256>>>(out);
}

// round 17
// speedup vs baseline: 1.1077x; 1.0317x over previous
#include <cuda_runtime.h>
#include <cuda_bf16.h>
#include <cstdint>

#define N_BATCH 4
#define C_DIM   512
#define C_W     256            // C_DIM/2 f16x2 words per row
#define T_DIM   4096
#define NTOK    (N_BATCH * T_DIM)   // 16384
#define H_HEADS 8
#define DH      64
#define CHUNK_SZ 64
#define NEG_INF (-1e9f)

// ---------------- fp16 GEMM tiling (R11-verified) --------------------------------
#define PBM 128
#define PBN 128
#define NKT (C_DIM / 32)       // 16 k-tiles of 32
#define WPITCH 20              // u32 per smem row (80 B)
#define A_U32 (128 * WPITCH)   // 2560
#define STAGE32 (2 * A_U32)    // A+B one stage: 5120 u32 (20 KB)
#define NSTAGE 3
#define OSMEM_BYTES (NSTAGE * STAGE32 * 4)   // 61440

// ---------------- attention tiling -----------------------------------------------
// Q/K rows hold DH=64 f16 = 128 B -> pitch 144 B (36 u32), R12-verified for LDSM
#define AQP 36
#define AQBUF (64 * AQP)       // 2304 u32 per buffer
#define AP2 68                 // V slot-layout pitch (verified)
#define ABUF2 (16 * AP2 * 2)   // 2176
#define ASMEM3 ((2 * AQBUF + ABUF2 + 64) * 4)   // 27392 B

// ---------------- scratch (fp16 packed as u32 words) -----------------------------
__device__ __align__(16) uint32_t g_QP16[(size_t)NTOK * C_W];
__device__ __align__(16) uint32_t g_KP16[(size_t)NTOK * C_W];
__device__ __align__(16) uint32_t g_VP16[(size_t)NTOK * C_W];
__device__ __align__(16) uint32_t g_AO16[(size_t)NTOK * C_W];
__device__ __align__(16) uint32_t g_W16[(size_t)2048 * C_W];   // 0-1535 Win, 1536-2047 Wout

// ---------------- helpers ---------------------------------------------------------
__device__ __forceinline__ uint32_t pack_f16x2(float lo, float hi) {
    uint32_t r;
    asm("cvt.rn.f16x2.f32 %0, %1, %2;" : "=r"(r) : "f"(hi), "f"(lo));
    return r;
}

__device__ __forceinline__ uint32_t prmt_u32(uint32_t a, uint32_t b, uint32_t sel) {
    uint32_t r;
    asm("prmt.b32 %0, %1, %2, %3;" : "=r"(r) : "r"(a), "r"(b), "r"(sel));
    return r;
}

__device__ __forceinline__ void mma_f16(float* c,
                                        uint32_t a0, uint32_t a1, uint32_t a2, uint32_t a3,
                                        uint32_t b0, uint32_t b1) {
    asm volatile(
        "mma.sync.aligned.m16n8k16.row.col.f32.f16.f16.f32 "
        "{%0,%1,%2,%3}, {%4,%5,%6,%7}, {%8,%9}, {%0,%1,%2,%3};\n"
        : "+f"(c[0]), "+f"(c[1]), "+f"(c[2]), "+f"(c[3])
        : "r"(a0), "r"(a1), "r"(a2), "r"(a3), "r"(b0), "r"(b1));
}

__device__ __forceinline__ void ldsm_x4(uint32_t& r0, uint32_t& r1, uint32_t& r2,
                                        uint32_t& r3, uint32_t addr) {
    asm volatile("ldmatrix.sync.aligned.m8n8.x4.shared.b16 {%0,%1,%2,%3}, [%4];"
                 : "=r"(r0), "=r"(r1), "=r"(r2), "=r"(r3) : "r"(addr));
}

#define CP_ASYNC16(dst, src) \
    asm volatile("cp.async.cg.shared.global [%0], [%1], 16;" :: "r"(dst), "l"(src))
#define CP_COMMIT() asm volatile("cp.async.commit_group;")
#define CP_WAIT0()  asm volatile("cp.async.wait_group 0;" ::: "memory")
#define CP_WAIT1()  asm volatile("cp.async.wait_group 1;" ::: "memory")

// ---- mma over one BK=32 stage, warp tile 64x64 (proj: 4 warps = 2m x 2n) --------
__device__ __forceinline__ void mma_tile_64x64(uint32_t sA, uint32_t sB,
                                               float acc[4][8][4],
                                               int wm, int wn, int lane) {
    int rA = wm * 64 + (lane & 7) + ((lane >> 3) & 1) * 8;
    int cA = ((lane >> 4) & 1) * 16;
    int rB = wn * 64 + (lane & 7) + ((lane >> 4) & 1) * 8;
    int cB = ((lane >> 3) & 1) * 16;
    #pragma unroll
    for (int ks = 0; ks < 2; ks++) {
        uint32_t a[4][4], b[4][4];
        #pragma unroll
        for (int mt = 0; mt < 4; mt++)
            ldsm_x4(a[mt][0], a[mt][1], a[mt][2], a[mt][3],
                    sA + (uint32_t)(rA + mt * 16) * 80 + cA + ks * 32);
        #pragma unroll
        for (int nt2 = 0; nt2 < 4; nt2++)
            ldsm_x4(b[nt2][0], b[nt2][1], b[nt2][2], b[nt2][3],
                    sB + (uint32_t)(rB + nt2 * 16) * 80 + cB + ks * 32);
        #pragma unroll
        for (int mt = 0; mt < 4; mt++)
            #pragma unroll
            for (int nt2 = 0; nt2 < 4; nt2++) {
                mma_f16(acc[mt][2 * nt2],     a[mt][0], a[mt][1], a[mt][2], a[mt][3],
                        b[nt2][0], b[nt2][1]);
                mma_f16(acc[mt][2 * nt2 + 1], a[mt][0], a[mt][1], a[mt][2], a[mt][3],
                        b[nt2][2], b[nt2][3]);
            }
    }
}

// ---- mma over one BK=32 stage, warp tile 64x32 (out: 8 warps = 2m x 4n) ---------
__device__ __forceinline__ void mma_tile_64x32(uint32_t sA, uint32_t sB,
                                               float acc[4][4][4],
                                               int wm, int wn, int lane) {
    int rA = wm * 64 + (lane & 7) + ((lane >> 3) & 1) * 8;
    int cA = ((lane >> 4) & 1) * 16;
    int rB = wn * 32 + (lane & 7) + ((lane >> 4) & 1) * 8;
    int cB = ((lane >> 3) & 1) * 16;
    #pragma unroll
    for (int ks = 0; ks < 2; ks++) {
        uint32_t a[4][4], b[2][4];
        #pragma unroll
        for (int mt = 0; mt < 4; mt++)
            ldsm_x4(a[mt][0], a[mt][1], a[mt][2], a[mt][3],
                    sA + (uint32_t)(rA + mt * 16) * 80 + cA + ks * 32);
        #pragma unroll
        for (int nb = 0; nb < 2; nb++)
            ldsm_x4(b[nb][0], b[nb][1], b[nb][2], b[nb][3],
                    sB + (uint32_t)(rB + nb * 16) * 80 + cB + ks * 32);
        #pragma unroll
        for (int mt = 0; mt < 4; mt++)
            #pragma unroll
            for (int nb = 0; nb < 2; nb++) {
                mma_f16(acc[mt][2 * nb],     a[mt][0], a[mt][1], a[mt][2], a[mt][3],
                        b[nb][0], b[nb][1]);
                mma_f16(acc[mt][2 * nb + 1], a[mt][0], a[mt][1], a[mt][2], a[mt][3],
                        b[nb][2], b[nb][3]);
            }
    }
}

// ---------------- weight pre-pack --------------------------------------------------
__global__ void pack_weights(const float* __restrict__ Win, const float* __restrict__ Wout)
{
    int i = blockIdx.x * 256 + threadIdx.x;
    int row = i >> 8, kw = i & 255;
    const float* src = (row < 1536) ? (Win + (size_t)row * C_DIM + 2 * kw)
                                    : (Wout + (size_t)(row - 1536) * C_DIM + 2 * kw);
    float2 f = *(const float2*)src;
    g_W16[i] = pack_f16x2(f.x, f.y);
}

// ---------------- GEMM: 3 projections (R8/R11-verified config) ---------------------
__global__ void __launch_bounds__(128, 2) gemm_proj_v2(
    const float* __restrict__ qin, const float* __restrict__ kin,
    const float* __restrict__ vin, const float* __restrict__ b_in)
{
    __shared__ __align__(16) uint32_t sm[2 * STAGE32];
    int z = blockIdx.z;
    const float* A = (z == 0) ? qin : (z == 1) ? kin : vin;
    uint32_t* Cout16 = (z == 0) ? g_QP16 : (z == 1) ? g_KP16 : g_VP16;
    const float* bias = b_in + z * C_DIM;

    int g0 = blockIdx.x * PBM, bn = blockIdx.y;
    int n = g0 / T_DIM, t0 = g0 % T_DIM;
    const float* Abase = A + (size_t)n * C_DIM * T_DIM + t0;
    const uint32_t* Wb = g_W16 + (size_t)(z * 512 + bn * PBN) * C_W;

    int tid = threadIdx.x, lane = tid & 31, wid = tid >> 5;
    int wm = wid >> 1, wn = wid & 1, q2 = lane & 3, rG = lane >> 2;
    uint32_t sbase = (uint32_t)__cvta_generic_to_shared(sm);

    float acc[4][8][4];
    #pragma unroll
    for (int a = 0; a < 4; a++)
        #pragma unroll
        for (int b = 0; b < 8; b++)
            #pragma unroll
            for (int c = 0; c < 4; c++) acc[a][b][c] = 0.f;

    int m0 = (tid & 31) * 4, kw0 = (tid >> 5) * 4;
    float4 av[8];

    // prologue: stage 0
    {
        int c0 = 2 * kw0;
        #pragma unroll
        for (int cr = 0; cr < 8; cr++)
            av[cr] = *(const float4*)(Abase + (size_t)(c0 + cr) * T_DIM + m0);
        uint32_t d = sbase + A_U32 * 4 + tid * 80;
        const uint32_t* s = Wb + (size_t)tid * C_W;
        #pragma unroll
        for (int ch = 0; ch < 4; ch++) CP_ASYNC16(d + ch * 16, s + ch * 4);
        CP_COMMIT();
        const float* fv = (const float*)av;
        #pragma unroll
        for (int i = 0; i < 4; i++) {
            uint4 u;
            u.x = pack_f16x2(fv[0 + i],  fv[4 + i]);
            u.y = pack_f16x2(fv[8 + i],  fv[12 + i]);
            u.z = pack_f16x2(fv[16 + i], fv[20 + i]);
            u.w = pack_f16x2(fv[24 + i], fv[28 + i]);
            *(uint4*)(sm + (m0 + i) * WPITCH + kw0) = u;
        }
    }
    CP_WAIT0();
    __syncthreads();

    for (int kt = 0; kt < NKT; kt++) {
        int p = kt & 1;
        if (kt + 1 < NKT) {
            int c0 = (kt + 1) * 32 + 2 * kw0;
            #pragma unroll
            for (int cr = 0; cr < 8; cr++)
                av[cr] = *(const float4*)(Abase + (size_t)(c0 + cr) * T_DIM + m0);
            uint32_t d = sbase + ((p ^ 1) * STAGE32 + A_U32) * 4 + tid * 80;
            const uint32_t* s = Wb + (size_t)tid * C_W + (kt + 1) * 16;
            #pragma unroll
            for (int ch = 0; ch < 4; ch++) CP_ASYNC16(d + ch * 16, s + ch * 4);
            CP_COMMIT();
        }
        mma_tile_64x64(sbase + p * STAGE32 * 4, sbase + (p * STAGE32 + A_U32) * 4,
                       acc, wm, wn, lane);
        if (kt + 1 < NKT) {
            uint32_t* buf = sm + (p ^ 1) * STAGE32;
            const float* fv = (const float*)av;
            #pragma unroll
            for (int i = 0; i < 4; i++) {
                uint4 u;
                u.x = pack_f16x2(fv[0 + i],  fv[4 + i]);
                u.y = pack_f16x2(fv[8 + i],  fv[12 + i]);
                u.z = pack_f16x2(fv[16 + i], fv[20 + i]);
                u.w = pack_f16x2(fv[24 + i], fv[28 + i]);
                *(uint4*)(buf + (m0 + i) * WPITCH + kw0) = u;
            }
            CP_WAIT0();
        }
        __syncthreads();
    }

    // epilogue: packed fp16 output [g][cw]
    #pragma unroll
    for (int nt = 0; nt < 8; nt++) {
        int cb = bn * PBN + wn * 64 + nt * 8 + 2 * q2;
        float b0 = bias[cb], b1 = bias[cb + 1];
        int wi = cb >> 1;
        #pragma unroll
        for (int mt = 0; mt < 4; mt++) {
            int r = g0 + wm * 64 + mt * 16 + rG;
            Cout16[(size_t)r * C_W + wi]       = pack_f16x2(acc[mt][nt][0] + b0, acc[mt][nt][1] + b1);
            Cout16[(size_t)(r + 8) * C_W + wi] = pack_f16x2(acc[mt][nt][2] + b0, acc[mt][nt][3] + b1);
        }
    }
}

// ---------------- GEMM: out-proj (R10/R11-verified v4) -----------------------------
__global__ void __launch_bounds__(256, 2) gemm_out_v4(
    const float* __restrict__ bias, const float* __restrict__ masks,
    const float* __restrict__ x, float* __restrict__ out)
{
    extern __shared__ uint32_t smd[];
    int g0 = blockIdx.x * PBM, bn = blockIdx.y;
    int n = g0 / T_DIM, t0 = g0 % T_DIM;
    const uint32_t* Ab = g_AO16 + (size_t)g0 * C_W;
    const uint32_t* Wb = g_W16 + (size_t)(1536 + bn * PBN) * C_W;

    int tid = threadIdx.x, lane = tid & 31, wid = tid >> 5;
    int wm = wid >> 2, wn = wid & 3, q2 = lane & 3, rG = lane >> 2;
    uint32_t sbase = (uint32_t)__cvta_generic_to_shared(smd);

    float acc[4][4][4];
    #pragma unroll
    for (int a = 0; a < 4; a++)
        #pragma unroll
        for (int b = 0; b < 4; b++)
            #pragma unroll
            for (int c = 0; c < 4; c++) acc[a][b][c] = 0.f;

    int row = tid >> 1, ch = (tid & 1) * 2;

    #pragma unroll
    for (int s = 0; s < 2; s++) {
        uint32_t dA = sbase + s * STAGE32 * 4 + row * 80 + ch * 16;
        uint32_t dB = dA + A_U32 * 4;
        const uint32_t* sA = Ab + (size_t)row * C_W + s * 16 + ch * 4;
        const uint32_t* sB = Wb + (size_t)row * C_W + s * 16 + ch * 4;
        CP_ASYNC16(dA, sA);
        CP_ASYNC16(dA + 16, sA + 4);
        CP_ASYNC16(dB, sB);
        CP_ASYNC16(dB + 16, sB + 4);
        CP_COMMIT();
    }

    for (int kt = 0; kt < NKT; kt++) {
        if (kt + 1 < NKT) CP_WAIT1(); else CP_WAIT0();
        __syncthreads();
        if (kt + 2 < NKT) {
            int st = (kt + 2) % NSTAGE;
            uint32_t dA = sbase + st * STAGE32 * 4 + row * 80 + ch * 16;
            uint32_t dB = dA + A_U32 * 4;
            const uint32_t* sA = Ab + (size_t)row * C_W + (kt + 2) * 16 + ch * 4;
            const uint32_t* sB = Wb + (size_t)row * C_W + (kt + 2) * 16 + ch * 4;
            CP_ASYNC16(dA, sA);
            CP_ASYNC16(dA + 16, sA + 4);
            CP_ASYNC16(dB, sB);
            CP_ASYNC16(dB + 16, sB + 4);
            CP_COMMIT();
        }
        int p = kt % NSTAGE;
        mma_tile_64x32(sbase + p * STAGE32 * 4, sbase + (p * STAGE32 + A_U32) * 4,
                       acc, wm, wn, lane);
    }

    #pragma unroll
    for (int mt = 0; mt < 4; mt++) {
        int r = wm * 64 + mt * 16 + rG;
        int tA = t0 + r;
        float mkA = masks[(size_t)n * T_DIM + tA];
        float mkB = masks[(size_t)n * T_DIM + tA + 8];
        #pragma unroll
        for (int nt = 0; nt < 4; nt++) {
            int co = bn * PBN + wn * 32 + nt * 8 + 2 * q2;
            #pragma unroll
            for (int cj = 0; cj < 2; cj++) {
                float bb = bias[co + cj];
                size_t iA = ((size_t)(n * C_DIM + co + cj)) * T_DIM + tA;
                out[iA]     = (acc[mt][nt][cj]     + bb) * mkA + x[iA];
                out[iA + 8] = (acc[mt][nt][2 + cj] + bb) * mkB + x[iA + 8];
            }
        }
    }
}

// ---------------- attention v2: cp.async Q/K (144B pitch) + register P -------------
__global__ void __launch_bounds__(128) attn_f16(const float* __restrict__ masks)
{
    extern __shared__ uint32_t ash[];
    uint32_t* sV = ash + 2 * AQBUF;             // verified slot layout
    float* skm   = (float*)(ash + 2 * AQBUF + ABUF2);

    int cb = blockIdx.x, h = blockIdx.y;
    int g0 = cb * CHUNK_SZ;
    int n = g0 / T_DIM, t0 = g0 % T_DIM;
    int tid = threadIdx.x, lane = tid & 31, w = tid >> 5;
    int q = lane & 3, rG = lane >> 2;
    uint32_t sbase = (uint32_t)__cvta_generic_to_shared(ash);
    uint32_t qb = sbase;                        // sQ: 64 rows x 144 B
    uint32_t kb = sbase + AQBUF * 4;            // sK

    if (tid < 64)
        skm[tid] = (masks[(size_t)n * T_DIM + t0 + tid] > 0.f) ? 0.f : NEG_INF;

    // Q,K: direct cp.async copies (pre-packed fp16 words, 128B data per row)
    {
        int m = tid >> 1, half = tid & 1;
        uint32_t dQ = qb + (uint32_t)m * 144 + half * 64;
        uint32_t dK = kb + (uint32_t)m * 144 + half * 64;
        const uint32_t* qp = g_QP16 + (size_t)(g0 + m) * C_W + h * 32 + half * 16;
        const uint32_t* kp = g_KP16 + (size_t)(g0 + m) * C_W + h * 32 + half * 16;
        #pragma unroll
        for (int j = 0; j < 4; j++) {
            CP_ASYNC16(dQ + j * 16, qp + j * 4);
            CP_ASYNC16(dK + j * 16, kp + j * 4);
        }
        CP_COMMIT();
    }
    // V^T: verified prmt-transpose into slot layout
    {
        int tp = tid >> 2;
        int w0 = (tid & 3) * 8;
        const uint32_t* r0 = g_VP16 + (size_t)(g0 + 2 * tp) * C_W + h * 32 + w0;
        const uint32_t* r1 = r0 + C_W;
        int slot = (tp >> 3) * 4 + (tp & 3);
        int kh = (tp >> 2) & 1;
        uint32_t* dst = sV + ((uint32_t)slot * AP2 + 2 * w0) * 2 + kh;
        #pragma unroll
        for (int half = 0; half < 2; half++) {
            uint4 a = *(const uint4*)(r0 + half * 4);
            uint4 b = *(const uint4*)(r1 + half * 4);
            const uint32_t* aw = (const uint32_t*)&a;
            const uint32_t* bw = (const uint32_t*)&b;
            #pragma unroll
            for (int j = 0; j < 4; j++) {
                dst[(half * 8 + 2 * j) * 2]     = prmt_u32(aw[j], bw[j], 0x5410);
                dst[(half * 8 + 2 * j + 1) * 2] = prmt_u32(aw[j], bw[j], 0x7632);
            }
        }
    }
    CP_WAIT0();
    __syncthreads();

    int mA = w * 16 + rG;

    // ---- S = Q K^T via ldmatrix ----
    float s[8][4];
    #pragma unroll
    for (int nt = 0; nt < 8; nt++)
        #pragma unroll
        for (int j = 0; j < 4; j++) s[nt][j] = 0.f;
    {
        int rA = w * 16 + (lane & 7) + ((lane >> 3) & 1) * 8;
        int cA = ((lane >> 4) & 1) * 16;
        int rB = (lane & 7) + ((lane >> 4) & 1) * 8;
        int cB = ((lane >> 3) & 1) * 16;
        #pragma unroll
        for (int ks = 0; ks < 4; ks++) {
            uint32_t a[4];
            ldsm_x4(a[0], a[1], a[2], a[3],
                    qb + (uint32_t)rA * 144 + cA + ks * 32);
            #pragma unroll
            for (int nt2 = 0; nt2 < 4; nt2++) {
                uint32_t b[4];
                ldsm_x4(b[0], b[1], b[2], b[3],
                        kb + (uint32_t)(rB + nt2 * 16) * 144 + cB + ks * 32);
                mma_f16(s[2 * nt2],     a[0], a[1], a[2], a[3], b[0], b[1]);
                mma_f16(s[2 * nt2 + 1], a[0], a[1], a[2], a[3], b[2], b[3]);
            }
        }
    }

    // ---- softmax in registers ----
    const float scale = 0.125f;
    float mxA = -3.4e38f, mxB = -3.4e38f;
    #pragma unroll
    for (int nt = 0; nt < 8; nt++) {
        int c0 = nt * 8 + 2 * q;
        float a0 = skm[c0], a1 = skm[c0 + 1];
        s[nt][0] = s[nt][0] * scale + a0;
        s[nt][1] = s[nt][1] * scale + a1;
        s[nt][2] = s[nt][2] * scale + a0;
        s[nt][3] = s[nt][3] * scale + a1;
        mxA = fmaxf(mxA, fmaxf(s[nt][0], s[nt][1]));
        mxB = fmaxf(mxB, fmaxf(s[nt][2], s[nt][3]));
    }
    mxA = fmaxf(mxA, __shfl_xor_sync(0xffffffffu, mxA, 1));
    mxA = fmaxf(mxA, __shfl_xor_sync(0xffffffffu, mxA, 2));
    mxB = fmaxf(mxB, __shfl_xor_sync(0xffffffffu, mxB, 1));
    mxB = fmaxf(mxB, __shfl_xor_sync(0xffffffffu, mxB, 2));
    float sA = 0.f, sB = 0.f;
    #pragma unroll
    for (int nt = 0; nt < 8; nt++) {
        s[nt][0] = __expf(s[nt][0] - mxA);
        s[nt][1] = __expf(s[nt][1] - mxA);
        s[nt][2] = __expf(s[nt][2] - mxB);
        s[nt][3] = __expf(s[nt][3] - mxB);
        sA += s[nt][0] + s[nt][1];
        sB += s[nt][2] + s[nt][3];
    }
    sA += __shfl_xor_sync(0xffffffffu, sA, 1);
    sA += __shfl_xor_sync(0xffffffffu, sA, 2);
    sB += __shfl_xor_sync(0xffffffffu, sB, 1);
    sB += __shfl_xor_sync(0xffffffffu, sB, 2);
    float iA = 1.f / sA, iB = 1.f / sB;
    #pragma unroll
    for (int nt = 0; nt < 8; nt++) {
        s[nt][0] *= iA; s[nt][1] *= iA;
        s[nt][2] *= iB; s[nt][3] *= iB;
    }

    // ---- O = P V with P kept in registers (C-frag == A-frag mapping) ----
    float o[8][4];
    #pragma unroll
    for (int nt = 0; nt < 8; nt++)
        #pragma unroll
        for (int j = 0; j < 4; j++) o[nt][j] = 0.f;
    #pragma unroll
    for (int ks = 0; ks < 4; ks++) {
        uint32_t a0 = pack_f16x2(s[2 * ks][0],     s[2 * ks][1]);
        uint32_t a1 = pack_f16x2(s[2 * ks][2],     s[2 * ks][3]);
        uint32_t a2 = pack_f16x2(s[2 * ks + 1][0], s[2 * ks + 1][1]);
        uint32_t a3 = pack_f16x2(s[2 * ks + 1][2], s[2 * ks + 1][3]);
        const uint32_t* Bb = sV + ((uint32_t)(ks * 4 + q) * AP2) * 2;
        #pragma unroll
        for (int nt = 0; nt < 8; nt++) {
            uint2 bb = *(const uint2*)(Bb + (nt * 8 + rG) * 2);
            mma_f16(o[nt], a0, a1, a2, a3, bb.x, bb.y);
        }
    }

    // ---- store O packed fp16 to g_AO16 ----
    uint32_t* aoA = g_AO16 + (size_t)(g0 + mA) * C_W + h * 32;
    uint32_t* aoB = g_AO16 + (size_t)(g0 + mA + 8) * C_W + h * 32;
    #pragma unroll
    for (int nt = 0; nt < 8; nt++) {
        aoA[nt * 4 + q] = pack_f16x2(o[nt][0], o[nt][1]);
        aoB[nt * 4 + q] = pack_f16x2(o[nt][2], o[nt][3]);
    }
}

// ---------------- InstanceNorm1d over T per (n,c) row -------------------------------
__global__ void __launch_bounds__(256) inorm_kernel(float* __restrict__ out)
{
    __shared__ float red[18];
    int row = blockIdx.x;
    float* p = out + (size_t)row * T_DIM;
    int tid = threadIdx.x;

    float4 v[4];
    float s = 0.f, s2 = 0.f;
    #pragma unroll
    for (int i = 0; i < 4; i++) {
        v[i] = *(const float4*)(p + i * 1024 + tid * 4);
        s  += v[i].x + v[i].y + v[i].z + v[i].w;
        s2 += v[i].x * v[i].x + v[i].y * v[i].y + v[i].z * v[i].z + v[i].w * v[i].w;
    }
    #pragma unroll
    for (int o = 16; o; o >>= 1) {
        s  += __shfl_xor_sync(0xffffffffu, s,  o);
        s2 += __shfl_xor_sync(0xffffffffu, s2, o);
    }
    int warp = tid >> 5, lane = tid & 31;
    if (lane == 0) { red[warp] = s; red[8 + warp] = s2; }
    __syncthreads();
    if (warp == 0) {
        float a  = (lane < 8) ? red[lane]     : 0.f;
        float a2 = (lane < 8) ? red[8 + lane] : 0.f;
        #pragma unroll
        for (int o = 4; o; o >>= 1) {
            a  += __shfl_xor_sync(0xffffffffu, a,  o);
            a2 += __shfl_xor_sync(0xffffffffu, a2, o);
        }
        if (lane == 0) { red[16] = a; red[17] = a2; }
    }
    __syncthreads();
    float mu  = red[16] * (1.f / T_DIM);
    float var = red[17] * (1.f / T_DIM) - mu * mu;
    float rs  = rsqrtf(var + 1e-5f);
    #pragma unroll
    for (int i = 0; i < 4; i++) {
        float4 r;
        r.x = (v[i].x - mu) * rs; r.y = (v[i].y - mu) * rs;
        r.z = (v[i].z - mu) * rs; r.w = (v[i].w - mu) * rs;
        *(float4*)(p + i * 1024 + tid * 4) = r;
    }
}

// ---------------- launch -------------------------------------------------------------
extern "C" void kernel_launch(void* const* d_in, const int* in_sizes, int n_in,
                              void* d_out, int out_size)
{
    const float* x     = (const float*)d_in[0];
    const float* q     = (const float*)d_in[1];
    const float* k     = (const float*)d_in[2];
    const float* v     = (const float*)d_in[3];
    const float* masks = (const float*)d_in[4];
    const float* W_in  = (const float*)d_in[5];
    const float* b_in  = (const float*)d_in[6];
    const float* W_out = (const float*)d_in[7];
    const float* b_out = (const float*)d_in[8];
    float* out = (float*)d_out;

    cudaFuncSetAttribute(attn_f16, cudaFuncAttributeMaxDynamicSharedMemorySize,
                         ASMEM3);
    cudaFuncSetAttribute(gemm_out_v4, cudaFuncAttributeMaxDynamicSharedMemorySize,
                         OSMEM_BYTES);

    pack_weights<<<2048, 256>>>(W_in, W_out);

    dim3 gp(NTOK / PBM, C_DIM / PBN, 3);   // (128, 4, 3)
    gemm_proj_v2<<<gp, 128>>>(q, k, v, b_in);

    attn_f16<<<dim3(NTOK / CHUNK_SZ, H_HEADS), 128, ASMEM3>>>(masks);

    dim3 gg(NTOK / PBM, C_DIM / PBN);      // (128, 4)
    gemm_out_v4<<<gg, 256, OSMEM_BYTES>>>(b_out, masks, x, out);

    inorm_kernel<<<N_BATCH * C_DIM, 256>>>(out);
}